// round 1
// baseline (speedup 1.0000x reference)
#include <cuda_runtime.h>
#include <math.h>
#include <float.h>

#define L_SEQ 2048
#define D_MODEL 1024
#define NH 16
#define DH 64
#define NB 2
#define M_TOK (NB * L_SEQ)  // 4096

// Scratch (allocation-free rule: __device__ globals)
__device__ float g_q[(size_t)M_TOK * D_MODEL];
__device__ float g_k[(size_t)M_TOK * D_MODEL];
__device__ float g_v[(size_t)M_TOK * D_MODEL];
__device__ float g_c[(size_t)M_TOK * D_MODEL];

// ---------------------------------------------------------------------------
// Tiled SGEMM: C[M,N] = A[M,K] @ B[K,N], all row-major fp32.
// 128x128 block, K-tile 8, 256 threads, 8x8 per-thread tile, register prefetch.
// M,N multiples of 128; K multiple of 8 (true for this problem).
// ---------------------------------------------------------------------------
__global__ __launch_bounds__(256) void sgemm128(const float* __restrict__ A,
                                                const float* __restrict__ B,
                                                float* __restrict__ C,
                                                int M, int N, int K) {
    __shared__ float As[8][128];
    __shared__ float Bs[8][128];

    const int tid = threadIdx.x;
    const int tx = tid & 15;   // col group (8 cols each)
    const int ty = tid >> 4;   // row group (8 rows each)
    const int bx = blockIdx.x; // over N
    const int by = blockIdx.y; // over M

    const int aRow = tid >> 1;
    const int aK = (tid & 1) * 4;
    const int bK = tid >> 5;
    const int bCol = (tid & 31) * 4;

    const float* Ag = A + (size_t)(by * 128 + aRow) * K + aK;
    const float* Bg = B + (size_t)bK * N + bx * 128 + bCol;

    float acc[8][8];
#pragma unroll
    for (int i = 0; i < 8; i++)
#pragma unroll
        for (int j = 0; j < 8; j++) acc[i][j] = 0.f;

    float4 av = *(const float4*)(Ag);
    float4 bv = *(const float4*)(Bg);

    for (int k0 = 0; k0 < K; k0 += 8) {
        As[aK + 0][aRow] = av.x;
        As[aK + 1][aRow] = av.y;
        As[aK + 2][aRow] = av.z;
        As[aK + 3][aRow] = av.w;
        *(float4*)&Bs[bK][bCol] = bv;
        __syncthreads();

        // prefetch next tile while computing
        float4 avn = av, bvn = bv;
        if (k0 + 8 < K) {
            avn = *(const float4*)(Ag + k0 + 8);
            bvn = *(const float4*)(Bg + (size_t)(k0 + 8) * N);
        }

#pragma unroll
        for (int kk = 0; kk < 8; kk++) {
            float a[8], b[8];
#pragma unroll
            for (int i = 0; i < 8; i++) a[i] = As[kk][ty * 8 + i];
#pragma unroll
            for (int j = 0; j < 8; j++) b[j] = Bs[kk][tx * 8 + j];
#pragma unroll
            for (int i = 0; i < 8; i++)
#pragma unroll
                for (int j = 0; j < 8; j++) acc[i][j] = fmaf(a[i], b[j], acc[i][j]);
        }
        __syncthreads();
        av = avn;
        bv = bvn;
    }

#pragma unroll
    for (int i = 0; i < 8; i++) {
        float* Cp = C + (size_t)(by * 128 + ty * 8 + i) * N + bx * 128 + tx * 8;
        *(float4*)Cp = make_float4(acc[i][0], acc[i][1], acc[i][2], acc[i][3]);
        *(float4*)(Cp + 4) = make_float4(acc[i][4], acc[i][5], acc[i][6], acc[i][7]);
    }
}

// ---------------------------------------------------------------------------
// Flash attention, fp32, BM=BN=64, dh=64.
// grid = (L/64, B*H); 256 threads: ty=tid/16 -> 4 query rows, tx=tid%16 -> 4
// cols (of S) / 4 dh lanes (of O). Row reductions via shfl over the 16-lane
// tx group (lanes (ty%2)*16..+16, xor masks 1..8 stay inside the group).
//
// Masking matches the reference EXACTLY: reference computes
// (qk + (-FLT_MAX)*p_mask)/sqrt(1024); in fp32 qk+(-FLT_MAX) rounds to
// -FLT_MAX, so masked logits are the constant -FLT_MAX*0.03125. Rows whose
// query is padded get ALL logits equal to that constant -> uniform softmax,
// which the online softmax reproduces (all-equal values -> weights 1/L).
// ---------------------------------------------------------------------------
__global__ __launch_bounds__(256) void attn64(const float* __restrict__ Qg_,
                                              const float* __restrict__ Kg_,
                                              const float* __restrict__ Vg_,
                                              const int* __restrict__ maskg,
                                              float* __restrict__ Ctx) {
    extern __shared__ float sm[];
    float* Qt = sm;                  // [64][65] Qt[k][r]   (Q transposed)
    float* KP = sm + 64 * 65;        // [64][65] Kt[k][c] then Pt[c][r]
    float* Vs = sm + 2 * 64 * 65;    // [64][68] Vs[c][d]
    int* mks = (int*)(sm + 2 * 64 * 65 + 64 * 68);  // [64] key mask tile

    const int tid = threadIdx.x;
    const int tx = tid & 15;
    const int ty = tid >> 4;
    const int q0 = blockIdx.x * 64;
    const int bh = blockIdx.y;
    const int b = bh >> 4;
    const int h = bh & 15;

    const float* Qg = Qg_ + (size_t)(b * L_SEQ + q0) * D_MODEL + h * DH;
    const float* Kg = Kg_ + (size_t)(b * L_SEQ) * D_MODEL + h * DH;
    const float* Vg = Vg_ + (size_t)(b * L_SEQ) * D_MODEL + h * DH;
    const int* mb = maskg + b * L_SEQ;

    // Load Q tile (64x64) transposed into Qt[k][r]
#pragma unroll
    for (int rep = 0; rep < 4; rep++) {
        int idx = tid + rep * 256;
        int r = idx >> 4;
        int k4 = (idx & 15) << 2;
        float4 v = *(const float4*)(Qg + (size_t)r * D_MODEL + k4);
        Qt[(k4 + 0) * 65 + r] = v.x;
        Qt[(k4 + 1) * 65 + r] = v.y;
        Qt[(k4 + 2) * 65 + r] = v.z;
        Qt[(k4 + 3) * 65 + r] = v.w;
    }

    int mq[4];
#pragma unroll
    for (int i = 0; i < 4; i++) mq[i] = mb[q0 + ty * 4 + i];

    float m_run[4], l_run[4], o[4][4];
#pragma unroll
    for (int i = 0; i < 4; i++) {
        m_run[i] = -FLT_MAX;
        l_run[i] = 0.f;
#pragma unroll
        for (int j = 0; j < 4; j++) o[i][j] = 0.f;
    }

    const float SCALE = 0.03125f;               // 1/sqrt(1024)
    const float MASKV = -FLT_MAX * 0.03125f;    // masked logit, exact vs ref

    for (int kt = 0; kt < L_SEQ / 64; kt++) {
        const int c0 = kt * 64;
        __syncthreads();  // prev-iteration Pt/Vs reads done before overwrite

        // Load K transposed -> KP[k][c], V -> Vs[c][d], key-mask tile
#pragma unroll
        for (int rep = 0; rep < 4; rep++) {
            int idx = tid + rep * 256;
            int r = idx >> 4;
            int k4 = (idx & 15) << 2;
            float4 kv = *(const float4*)(Kg + (size_t)(c0 + r) * D_MODEL + k4);
            KP[(k4 + 0) * 65 + r] = kv.x;
            KP[(k4 + 1) * 65 + r] = kv.y;
            KP[(k4 + 2) * 65 + r] = kv.z;
            KP[(k4 + 3) * 65 + r] = kv.w;
            float4 vv = *(const float4*)(Vg + (size_t)(c0 + r) * D_MODEL + k4);
            *(float4*)&Vs[r * 68 + k4] = vv;
        }
        if (tid < 64) mks[tid] = mb[c0 + tid];
        __syncthreads();

        // S = Q K^T for this thread's 4x4 subtile
        float s[4][4];
#pragma unroll
        for (int i = 0; i < 4; i++)
#pragma unroll
            for (int j = 0; j < 4; j++) s[i][j] = 0.f;

#pragma unroll 8
        for (int k = 0; k < 64; k++) {
            float qv[4], kv[4];
#pragma unroll
            for (int i = 0; i < 4; i++) qv[i] = Qt[k * 65 + ty * 4 + i];
#pragma unroll
            for (int j = 0; j < 4; j++) kv[j] = KP[k * 65 + tx * 4 + j];
#pragma unroll
            for (int i = 0; i < 4; i++)
#pragma unroll
                for (int j = 0; j < 4; j++) s[i][j] = fmaf(qv[i], kv[j], s[i][j]);
        }

        int mk4[4];
#pragma unroll
        for (int j = 0; j < 4; j++) mk4[j] = mks[tx * 4 + j];
#pragma unroll
        for (int i = 0; i < 4; i++)
#pragma unroll
            for (int j = 0; j < 4; j++)
                s[i][j] = (mq[i] && mk4[j]) ? s[i][j] * SCALE : MASKV;

        // online softmax: row max / exp / row sum (reduce over 16-lane group)
        float mx[4];
#pragma unroll
        for (int i = 0; i < 4; i++) {
            mx[i] = fmaxf(fmaxf(s[i][0], s[i][1]), fmaxf(s[i][2], s[i][3]));
        }
#pragma unroll
        for (int off = 1; off < 16; off <<= 1)
#pragma unroll
            for (int i = 0; i < 4; i++)
                mx[i] = fmaxf(mx[i], __shfl_xor_sync(0xffffffffu, mx[i], off));

        float mnew[4], corr[4], rs[4];
#pragma unroll
        for (int i = 0; i < 4; i++) {
            mnew[i] = fmaxf(m_run[i], mx[i]);
            corr[i] = __expf(m_run[i] - mnew[i]);
            rs[i] = 0.f;
#pragma unroll
            for (int j = 0; j < 4; j++) {
                s[i][j] = __expf(s[i][j] - mnew[i]);
                rs[i] += s[i][j];
            }
        }
#pragma unroll
        for (int off = 1; off < 16; off <<= 1)
#pragma unroll
            for (int i = 0; i < 4; i++)
                rs[i] += __shfl_xor_sync(0xffffffffu, rs[i], off);
#pragma unroll
        for (int i = 0; i < 4; i++) {
            l_run[i] = l_run[i] * corr[i] + rs[i];
            m_run[i] = mnew[i];
#pragma unroll
            for (int j = 0; j < 4; j++) o[i][j] *= corr[i];
        }

        __syncthreads();  // all S reads of KP done -> safe to overwrite with Pt
        // write P transposed: Pt[c][r]
#pragma unroll
        for (int j = 0; j < 4; j++)
#pragma unroll
            for (int i = 0; i < 4; i++)
                KP[(tx * 4 + j) * 65 + ty * 4 + i] = s[i][j];
        __syncthreads();

        // O += P @ V
#pragma unroll 8
        for (int c = 0; c < 64; c++) {
            float pv[4];
#pragma unroll
            for (int i = 0; i < 4; i++) pv[i] = KP[c * 65 + ty * 4 + i];
            float4 vvv = *(const float4*)&Vs[c * 68 + tx * 4];
            float vv[4] = {vvv.x, vvv.y, vvv.z, vvv.w};
#pragma unroll
            for (int i = 0; i < 4; i++)
#pragma unroll
                for (int j = 0; j < 4; j++) o[i][j] = fmaf(pv[i], vv[j], o[i][j]);
        }
    }

    // epilogue: normalize + write ctx in [token][h*64+d] layout
#pragma unroll
    for (int i = 0; i < 4; i++) {
        float inv = 1.0f / l_run[i];
        float4 r = make_float4(o[i][0] * inv, o[i][1] * inv, o[i][2] * inv,
                               o[i][3] * inv);
        *(float4*)&Ctx[(size_t)(b * L_SEQ + q0 + ty * 4 + i) * D_MODEL + h * DH +
                       tx * 4] = r;
    }
}

// ---------------------------------------------------------------------------
extern "C" void kernel_launch(void* const* d_in, const int* in_sizes, int n_in,
                              void* d_out, int out_size) {
    const float* x = (const float*)d_in[0];
    const int* mask = (const int*)d_in[1];
    const float* wq = (const float*)d_in[2];
    const float* wk = (const float*)d_in[3];
    const float* wv = (const float*)d_in[4];
    const float* wo = (const float*)d_in[5];
    float* out = (float*)d_out;

    float *q, *k, *v, *c;
    cudaGetSymbolAddress((void**)&q, g_q);
    cudaGetSymbolAddress((void**)&k, g_k);
    cudaGetSymbolAddress((void**)&v, g_v);
    cudaGetSymbolAddress((void**)&c, g_c);

    dim3 gemmGrid(D_MODEL / 128, M_TOK / 128);
    sgemm128<<<gemmGrid, 256>>>(x, wq, q, M_TOK, D_MODEL, D_MODEL);
    sgemm128<<<gemmGrid, 256>>>(x, wk, k, M_TOK, D_MODEL, D_MODEL);
    sgemm128<<<gemmGrid, 256>>>(x, wv, v, M_TOK, D_MODEL, D_MODEL);

    size_t smem = (size_t)(2 * 64 * 65 + 64 * 68) * sizeof(float) + 64 * sizeof(int);
    cudaFuncSetAttribute(attn64, cudaFuncAttributeMaxDynamicSharedMemorySize,
                         (int)smem);
    attn64<<<dim3(L_SEQ / 64, NB * NH), 256, smem>>>(q, k, v, mask, c);

    sgemm128<<<gemmGrid, 256>>>(c, wo, out, M_TOK, D_MODEL, D_MODEL);
}

// round 3
// speedup vs baseline: 1.0183x; 1.0183x over previous
#include <cuda_runtime.h>
#include <cuda_bf16.h>
#include <math.h>
#include <float.h>
#include <stdint.h>

#define L_SEQ 2048
#define D_MODEL 1024
#define NH 16
#define DH 64
#define NB 2
#define M_TOK (NB * L_SEQ)  // 4096

// Scratch (allocation-free rule: __device__ globals)
__device__ float g_q[(size_t)M_TOK * D_MODEL];
__device__ float g_k[(size_t)M_TOK * D_MODEL];
__device__ float g_v[(size_t)M_TOK * D_MODEL];
__device__ float g_c[(size_t)M_TOK * D_MODEL];

// ===========================================================================
// bf16 split-precision GEMM on mma.sync (HMMA, legal on base sm_100 target).
// C[M,1024] = A[M,1024] @ W[1024,1024], fp32 in/out.
// a = a_hi + a_lo (bf16 each);  C = Ah*Bh + Ah*Bl + Al*Bh  (err ~2^-18).
// Block 128x128, k-tile 32, 256 thr = 8 warps in 4(m) x 2(n), warp 32x64.
// ===========================================================================
#define GK 1024
#define GN 1024
#define BKT 32
#define KPAD 40  // bf16 elems per smem row (32 + 8 pad)

__device__ __forceinline__ void mma_bf16(float* c, const uint32_t* a,
                                         const uint32_t* b) {
    asm volatile(
        "mma.sync.aligned.m16n8k16.row.col.f32.bf16.bf16.f32 "
        "{%0,%1,%2,%3}, {%4,%5,%6,%7}, {%8,%9}, {%0,%1,%2,%3};"
        : "+f"(c[0]), "+f"(c[1]), "+f"(c[2]), "+f"(c[3])
        : "r"(a[0]), "r"(a[1]), "r"(a[2]), "r"(a[3]), "r"(b[0]), "r"(b[1]));
}
__device__ __forceinline__ uint32_t pack2bf(float a, float b) {
    __nv_bfloat162 h = __floats2bfloat162_rn(a, b);
    return *reinterpret_cast<uint32_t*>(&h);
}

__global__ __launch_bounds__(256) void gemm_mma(const float* __restrict__ A,
                                                const float* __restrict__ W,
                                                float* __restrict__ C) {
    __shared__ __nv_bfloat16 Ah[128][KPAD];
    __shared__ __nv_bfloat16 Al[128][KPAD];
    __shared__ __nv_bfloat16 Bh[128][KPAD];  // rows = n, cols = k
    __shared__ __nv_bfloat16 Bl[128][KPAD];

    const int tid = threadIdx.x;
    const int wid = tid >> 5;
    const int lane = tid & 31;
    const int g = lane >> 2;       // group id 0..7
    const int tg = lane & 3;       // thread-in-group
    const int wm = (wid & 3) * 32; // warp m offset in block
    const int wn = (wid >> 2) * 64;
    const int m0 = blockIdx.y * 128;
    const int n0 = blockIdx.x * 128;

    float acc[2][8][4];
#pragma unroll
    for (int i = 0; i < 2; i++)
#pragma unroll
        for (int j = 0; j < 8; j++)
#pragma unroll
            for (int r = 0; r < 4; r++) acc[i][j][r] = 0.f;

    for (int k0 = 0; k0 < GK; k0 += BKT) {
        __syncthreads();
        // ---- load A tile 128x32 fp32, split into hi/lo bf16
        {
            float4 va[4];
#pragma unroll
            for (int i = 0; i < 4; i++) {
                int f = tid + i * 256;
                int row = f >> 3;
                int col = (f & 7) << 2;
                va[i] = *(const float4*)(A + (size_t)(m0 + row) * GK + k0 + col);
            }
#pragma unroll
            for (int i = 0; i < 4; i++) {
                int f = tid + i * 256;
                int row = f >> 3;
                int col = (f & 7) << 2;
                float4 v = va[i];
                __nv_bfloat16 h0 = __float2bfloat16(v.x);
                __nv_bfloat16 h1 = __float2bfloat16(v.y);
                __nv_bfloat16 h2 = __float2bfloat16(v.z);
                __nv_bfloat16 h3 = __float2bfloat16(v.w);
                uint2 hv, lv;
                {
                    __nv_bfloat162 p01; p01.x = h0; p01.y = h1;
                    __nv_bfloat162 p23; p23.x = h2; p23.y = h3;
                    hv.x = *reinterpret_cast<uint32_t*>(&p01);
                    hv.y = *reinterpret_cast<uint32_t*>(&p23);
                }
                lv.x = pack2bf(v.x - __bfloat162float(h0),
                               v.y - __bfloat162float(h1));
                lv.y = pack2bf(v.z - __bfloat162float(h2),
                               v.w - __bfloat162float(h3));
                *(uint2*)&Ah[row][col] = hv;
                *(uint2*)&Al[row][col] = lv;
            }
        }
        // ---- load B tile 32x128 fp32 (W[k][n]) -> Bs[n][k] hi/lo
        {
            float4 vb[4];
#pragma unroll
            for (int i = 0; i < 4; i++) {
                int f = tid + i * 256;
                int krow = f >> 5;
                int n = (f & 31) << 2;
                vb[i] = *(const float4*)(W + (size_t)(k0 + krow) * GN + n0 + n);
            }
#pragma unroll
            for (int i = 0; i < 4; i++) {
                int f = tid + i * 256;
                int krow = f >> 5;
                int n = (f & 31) << 2;
                float4 v = vb[i];
                float vv[4] = {v.x, v.y, v.z, v.w};
#pragma unroll
                for (int j = 0; j < 4; j++) {
                    __nv_bfloat16 h = __float2bfloat16(vv[j]);
                    Bh[n + j][krow] = h;
                    Bl[n + j][krow] = __float2bfloat16(vv[j] - __bfloat162float(h));
                }
            }
        }
        __syncthreads();

#pragma unroll
        for (int kh = 0; kh < 2; kh++) {  // two k16 steps per k-tile
            const int kb = kh * 16;
            // A fragments: 2 m-tiles, hi & lo
            uint32_t afh[2][4], afl[2][4];
#pragma unroll
            for (int mt = 0; mt < 2; mt++) {
                int r = wm + mt * 16 + g;
                int c = kb + 2 * tg;
                afh[mt][0] = *(const uint32_t*)&Ah[r][c];
                afh[mt][1] = *(const uint32_t*)&Ah[r + 8][c];
                afh[mt][2] = *(const uint32_t*)&Ah[r][c + 8];
                afh[mt][3] = *(const uint32_t*)&Ah[r + 8][c + 8];
                afl[mt][0] = *(const uint32_t*)&Al[r][c];
                afl[mt][1] = *(const uint32_t*)&Al[r + 8][c];
                afl[mt][2] = *(const uint32_t*)&Al[r][c + 8];
                afl[mt][3] = *(const uint32_t*)&Al[r + 8][c + 8];
            }
            // B fragments: 8 n-tiles, hi & lo
            uint32_t bfh[8][2], bfl[8][2];
#pragma unroll
            for (int nt = 0; nt < 8; nt++) {
                int n = wn + nt * 8 + g;
                int c = kb + 2 * tg;
                bfh[nt][0] = *(const uint32_t*)&Bh[n][c];
                bfh[nt][1] = *(const uint32_t*)&Bh[n][c + 8];
                bfl[nt][0] = *(const uint32_t*)&Bl[n][c];
                bfl[nt][1] = *(const uint32_t*)&Bl[n][c + 8];
            }
#pragma unroll
            for (int mt = 0; mt < 2; mt++)
#pragma unroll
                for (int nt = 0; nt < 8; nt++) {
                    mma_bf16(acc[mt][nt], afh[mt], bfh[nt]);
                    mma_bf16(acc[mt][nt], afh[mt], bfl[nt]);
                    mma_bf16(acc[mt][nt], afl[mt], bfh[nt]);
                }
        }
    }

    // epilogue: c frag rows g, g+8; cols 2*tg, 2*tg+1
#pragma unroll
    for (int mt = 0; mt < 2; mt++) {
        int rbase = m0 + wm + mt * 16 + g;
#pragma unroll
        for (int nt = 0; nt < 8; nt++) {
            int cbase = n0 + wn + nt * 8 + 2 * tg;
            float* p0 = C + (size_t)rbase * GN + cbase;
            float* p1 = C + (size_t)(rbase + 8) * GN + cbase;
            p0[0] = acc[mt][nt][0];
            p0[1] = acc[mt][nt][1];
            p1[0] = acc[mt][nt][2];
            p1[1] = acc[mt][nt][3];
        }
    }
}

// ---------------------------------------------------------------------------
// Flash attention, fp32, BM=BN=64, dh=64. (unchanged, known correct)
// ---------------------------------------------------------------------------
__global__ __launch_bounds__(256) void attn64(const float* __restrict__ Qg_,
                                              const float* __restrict__ Kg_,
                                              const float* __restrict__ Vg_,
                                              const int* __restrict__ maskg,
                                              float* __restrict__ Ctx) {
    extern __shared__ float sm[];
    float* Qt = sm;                  // [64][65]
    float* KP = sm + 64 * 65;        // [64][65]
    float* Vs = sm + 2 * 64 * 65;    // [64][68]
    int* mks = (int*)(sm + 2 * 64 * 65 + 64 * 68);

    const int tid = threadIdx.x;
    const int tx = tid & 15;
    const int ty = tid >> 4;
    const int q0 = blockIdx.x * 64;
    const int bh = blockIdx.y;
    const int b = bh >> 4;
    const int h = bh & 15;

    const float* Qg = Qg_ + (size_t)(b * L_SEQ + q0) * D_MODEL + h * DH;
    const float* Kg = Kg_ + (size_t)(b * L_SEQ) * D_MODEL + h * DH;
    const float* Vg = Vg_ + (size_t)(b * L_SEQ) * D_MODEL + h * DH;
    const int* mb = maskg + b * L_SEQ;

#pragma unroll
    for (int rep = 0; rep < 4; rep++) {
        int idx = tid + rep * 256;
        int r = idx >> 4;
        int k4 = (idx & 15) << 2;
        float4 v = *(const float4*)(Qg + (size_t)r * D_MODEL + k4);
        Qt[(k4 + 0) * 65 + r] = v.x;
        Qt[(k4 + 1) * 65 + r] = v.y;
        Qt[(k4 + 2) * 65 + r] = v.z;
        Qt[(k4 + 3) * 65 + r] = v.w;
    }

    int mq[4];
#pragma unroll
    for (int i = 0; i < 4; i++) mq[i] = mb[q0 + ty * 4 + i];

    float m_run[4], l_run[4], o[4][4];
#pragma unroll
    for (int i = 0; i < 4; i++) {
        m_run[i] = -FLT_MAX;
        l_run[i] = 0.f;
#pragma unroll
        for (int j = 0; j < 4; j++) o[i][j] = 0.f;
    }

    const float SCALE = 0.03125f;
    const float MASKV = -FLT_MAX * 0.03125f;

    for (int kt = 0; kt < L_SEQ / 64; kt++) {
        const int c0 = kt * 64;
        __syncthreads();

#pragma unroll
        for (int rep = 0; rep < 4; rep++) {
            int idx = tid + rep * 256;
            int r = idx >> 4;
            int k4 = (idx & 15) << 2;
            float4 kv = *(const float4*)(Kg + (size_t)(c0 + r) * D_MODEL + k4);
            KP[(k4 + 0) * 65 + r] = kv.x;
            KP[(k4 + 1) * 65 + r] = kv.y;
            KP[(k4 + 2) * 65 + r] = kv.z;
            KP[(k4 + 3) * 65 + r] = kv.w;
            float4 vv = *(const float4*)(Vg + (size_t)(c0 + r) * D_MODEL + k4);
            *(float4*)&Vs[r * 68 + k4] = vv;
        }
        if (tid < 64) mks[tid] = mb[c0 + tid];
        __syncthreads();

        float s[4][4];
#pragma unroll
        for (int i = 0; i < 4; i++)
#pragma unroll
            for (int j = 0; j < 4; j++) s[i][j] = 0.f;

#pragma unroll 8
        for (int k = 0; k < 64; k++) {
            float qv[4], kv[4];
#pragma unroll
            for (int i = 0; i < 4; i++) qv[i] = Qt[k * 65 + ty * 4 + i];
#pragma unroll
            for (int j = 0; j < 4; j++) kv[j] = KP[k * 65 + tx * 4 + j];
#pragma unroll
            for (int i = 0; i < 4; i++)
#pragma unroll
                for (int j = 0; j < 4; j++) s[i][j] = fmaf(qv[i], kv[j], s[i][j]);
        }

        int mk4[4];
#pragma unroll
        for (int j = 0; j < 4; j++) mk4[j] = mks[tx * 4 + j];
#pragma unroll
        for (int i = 0; i < 4; i++)
#pragma unroll
            for (int j = 0; j < 4; j++)
                s[i][j] = (mq[i] && mk4[j]) ? s[i][j] * SCALE : MASKV;

        float mx[4];
#pragma unroll
        for (int i = 0; i < 4; i++)
            mx[i] = fmaxf(fmaxf(s[i][0], s[i][1]), fmaxf(s[i][2], s[i][3]));
#pragma unroll
        for (int off = 1; off < 16; off <<= 1)
#pragma unroll
            for (int i = 0; i < 4; i++)
                mx[i] = fmaxf(mx[i], __shfl_xor_sync(0xffffffffu, mx[i], off));

        float mnew[4], corr[4], rs[4];
#pragma unroll
        for (int i = 0; i < 4; i++) {
            mnew[i] = fmaxf(m_run[i], mx[i]);
            corr[i] = __expf(m_run[i] - mnew[i]);
            rs[i] = 0.f;
#pragma unroll
            for (int j = 0; j < 4; j++) {
                s[i][j] = __expf(s[i][j] - mnew[i]);
                rs[i] += s[i][j];
            }
        }
#pragma unroll
        for (int off = 1; off < 16; off <<= 1)
#pragma unroll
            for (int i = 0; i < 4; i++)
                rs[i] += __shfl_xor_sync(0xffffffffu, rs[i], off);
#pragma unroll
        for (int i = 0; i < 4; i++) {
            l_run[i] = l_run[i] * corr[i] + rs[i];
            m_run[i] = mnew[i];
#pragma unroll
            for (int j = 0; j < 4; j++) o[i][j] *= corr[i];
        }

        __syncthreads();
#pragma unroll
        for (int j = 0; j < 4; j++)
#pragma unroll
            for (int i = 0; i < 4; i++)
                KP[(tx * 4 + j) * 65 + ty * 4 + i] = s[i][j];
        __syncthreads();

#pragma unroll 8
        for (int c = 0; c < 64; c++) {
            float pv[4];
#pragma unroll
            for (int i = 0; i < 4; i++) pv[i] = KP[c * 65 + ty * 4 + i];
            float4 vvv = *(const float4*)&Vs[c * 68 + tx * 4];
            float vv[4] = {vvv.x, vvv.y, vvv.z, vvv.w};
#pragma unroll
            for (int i = 0; i < 4; i++)
#pragma unroll
                for (int j = 0; j < 4; j++) o[i][j] = fmaf(pv[i], vv[j], o[i][j]);
        }
    }

#pragma unroll
    for (int i = 0; i < 4; i++) {
        float inv = 1.0f / l_run[i];
        float4 r = make_float4(o[i][0] * inv, o[i][1] * inv, o[i][2] * inv,
                               o[i][3] * inv);
        *(float4*)&Ctx[(size_t)(b * L_SEQ + q0 + ty * 4 + i) * D_MODEL + h * DH +
                       tx * 4] = r;
    }
}

// ---------------------------------------------------------------------------
extern "C" void kernel_launch(void* const* d_in, const int* in_sizes, int n_in,
                              void* d_out, int out_size) {
    const float* x = (const float*)d_in[0];
    const int* mask = (const int*)d_in[1];
    const float* wq = (const float*)d_in[2];
    const float* wk = (const float*)d_in[3];
    const float* wv = (const float*)d_in[4];
    const float* wo = (const float*)d_in[5];
    float* out = (float*)d_out;

    float *q, *k, *v, *c;
    cudaGetSymbolAddress((void**)&q, g_q);
    cudaGetSymbolAddress((void**)&k, g_k);
    cudaGetSymbolAddress((void**)&v, g_v);
    cudaGetSymbolAddress((void**)&c, g_c);

    dim3 gg(GN / 128, M_TOK / 128);  // (8, 32)
    gemm_mma<<<gg, 256>>>(x, wq, q);
    gemm_mma<<<gg, 256>>>(x, wk, k);
    gemm_mma<<<gg, 256>>>(x, wv, v);

    size_t smA = (size_t)(2 * 64 * 65 + 64 * 68) * sizeof(float) + 64 * sizeof(int);
    cudaFuncSetAttribute(attn64, cudaFuncAttributeMaxDynamicSharedMemorySize,
                         (int)smA);
    attn64<<<dim3(L_SEQ / 64, NB * NH), 256, smA>>>(q, k, v, mask, c);

    gemm_mma<<<gg, 256>>>(c, wo, out);
}

// round 6
// speedup vs baseline: 1.3602x; 1.3357x over previous
#include <cuda_runtime.h>
#include <cuda_bf16.h>
#include <math.h>
#include <float.h>
#include <stdint.h>

#define L_SEQ 2048
#define D_MODEL 1024
#define NH 16
#define DH 64
#define NB 2
#define M_TOK (NB * L_SEQ)  // 4096

// Scratch (__device__ globals; allocation-free rule)
__device__ __nv_bfloat16 g_qh[(size_t)M_TOK * D_MODEL];
__device__ __nv_bfloat16 g_ql[(size_t)M_TOK * D_MODEL];
__device__ __nv_bfloat16 g_kh[(size_t)M_TOK * D_MODEL];
__device__ __nv_bfloat16 g_kl[(size_t)M_TOK * D_MODEL];
__device__ __nv_bfloat16 g_vh[(size_t)M_TOK * D_MODEL];
__device__ __nv_bfloat16 g_vl[(size_t)M_TOK * D_MODEL];
__device__ float g_c[(size_t)M_TOK * D_MODEL];

// ===========================================================================
// common helpers
// ===========================================================================
__device__ __forceinline__ void mma_bf16(float* c, const uint32_t* a,
                                         const uint32_t* b) {
    asm volatile(
        "mma.sync.aligned.m16n8k16.row.col.f32.bf16.bf16.f32 "
        "{%0,%1,%2,%3}, {%4,%5,%6,%7}, {%8,%9}, {%0,%1,%2,%3};"
        : "+f"(c[0]), "+f"(c[1]), "+f"(c[2]), "+f"(c[3])
        : "r"(a[0]), "r"(a[1]), "r"(a[2]), "r"(a[3]), "r"(b[0]), "r"(b[1]));
}
__device__ __forceinline__ uint32_t pack2bf(float a, float b) {
    __nv_bfloat162 h = __floats2bfloat162_rn(a, b);
    return *reinterpret_cast<uint32_t*>(&h);
}
// split x,y into hi/lo bf16 packed words
__device__ __forceinline__ void split2(float x, float y, uint32_t& hi,
                                       uint32_t& lo) {
    __nv_bfloat16 hx = __float2bfloat16(x);
    __nv_bfloat16 hy = __float2bfloat16(y);
    __nv_bfloat162 hp;
    hp.x = hx; hp.y = hy;
    hi = *reinterpret_cast<uint32_t*>(&hp);
    lo = pack2bf(x - __bfloat162float(hx), y - __bfloat162float(hy));
}
// exp on the FMA pipe (no MUFU). x <= ~0. Exact 1.0 at x==0.
__device__ __forceinline__ float fexp(float x) {
    float y = x * 1.4426950408889634f;
    y = fmaxf(y, -126.0f);       // clamps -inf / huge-negative safely
    float n = rintf(y);
    float f = y - n;
    float t = f * 0.6931471805599453f;
    float p = 1.9841270e-4f;     // 1/5040
    p = fmaf(p, t, 1.3888889e-3f);
    p = fmaf(p, t, 8.3333333e-3f);
    p = fmaf(p, t, 4.1666668e-2f);
    p = fmaf(p, t, 0.16666667f);
    p = fmaf(p, t, 0.5f);
    p = fmaf(p, t, 1.0f);
    p = fmaf(p, t, 1.0f);
    return __int_as_float(__float_as_int(p) + ((int)n << 23));
}

// ===========================================================================
// bf16 split-precision GEMM on mma.sync. MODE 0: fp32 C. MODE 1: bf16 hi/lo.
// ===========================================================================
#define GK 1024
#define GN 1024
#define BKT 32
#define KPAD 40

template <int MODE>
__global__ __launch_bounds__(256) void gemm_mma(const float* __restrict__ A,
                                                const float* __restrict__ W,
                                                float* __restrict__ C,
                                                __nv_bfloat16* __restrict__ Chi,
                                                __nv_bfloat16* __restrict__ Clo) {
    __shared__ __nv_bfloat16 Ah[128][KPAD];
    __shared__ __nv_bfloat16 Al[128][KPAD];
    __shared__ __nv_bfloat16 Bh[128][KPAD];
    __shared__ __nv_bfloat16 Bl[128][KPAD];

    const int tid = threadIdx.x;
    const int wid = tid >> 5;
    const int lane = tid & 31;
    const int g = lane >> 2;
    const int tg = lane & 3;
    const int wm = (wid & 3) * 32;
    const int wn = (wid >> 2) * 64;
    const int m0 = blockIdx.y * 128;
    const int n0 = blockIdx.x * 128;

    float acc[2][8][4];
#pragma unroll
    for (int i = 0; i < 2; i++)
#pragma unroll
        for (int j = 0; j < 8; j++)
#pragma unroll
            for (int r = 0; r < 4; r++) acc[i][j][r] = 0.f;

    for (int k0 = 0; k0 < GK; k0 += BKT) {
        __syncthreads();
        {
            float4 va[4];
#pragma unroll
            for (int i = 0; i < 4; i++) {
                int f = tid + i * 256;
                int row = f >> 3;
                int col = (f & 7) << 2;
                va[i] = *(const float4*)(A + (size_t)(m0 + row) * GK + k0 + col);
            }
#pragma unroll
            for (int i = 0; i < 4; i++) {
                int f = tid + i * 256;
                int row = f >> 3;
                int col = (f & 7) << 2;
                float4 v = va[i];
                uint32_t h01, l01, h23, l23;
                split2(v.x, v.y, h01, l01);
                split2(v.z, v.w, h23, l23);
                *(uint2*)&Ah[row][col] = make_uint2(h01, h23);
                *(uint2*)&Al[row][col] = make_uint2(l01, l23);
            }
        }
        {
            float4 vb[4];
#pragma unroll
            for (int i = 0; i < 4; i++) {
                int f = tid + i * 256;
                int krow = f >> 5;
                int n = (f & 31) << 2;
                vb[i] = *(const float4*)(W + (size_t)(k0 + krow) * GN + n0 + n);
            }
#pragma unroll
            for (int i = 0; i < 4; i++) {
                int f = tid + i * 256;
                int krow = f >> 5;
                int n = (f & 31) << 2;
                float4 v = vb[i];
                float vv[4] = {v.x, v.y, v.z, v.w};
#pragma unroll
                for (int j = 0; j < 4; j++) {
                    __nv_bfloat16 h = __float2bfloat16(vv[j]);
                    Bh[n + j][krow] = h;
                    Bl[n + j][krow] = __float2bfloat16(vv[j] - __bfloat162float(h));
                }
            }
        }
        __syncthreads();

#pragma unroll
        for (int kh = 0; kh < 2; kh++) {
            const int kb = kh * 16;
            uint32_t afh[2][4], afl[2][4];
#pragma unroll
            for (int mt = 0; mt < 2; mt++) {
                int r = wm + mt * 16 + g;
                int c = kb + 2 * tg;
                afh[mt][0] = *(const uint32_t*)&Ah[r][c];
                afh[mt][1] = *(const uint32_t*)&Ah[r + 8][c];
                afh[mt][2] = *(const uint32_t*)&Ah[r][c + 8];
                afh[mt][3] = *(const uint32_t*)&Ah[r + 8][c + 8];
                afl[mt][0] = *(const uint32_t*)&Al[r][c];
                afl[mt][1] = *(const uint32_t*)&Al[r + 8][c];
                afl[mt][2] = *(const uint32_t*)&Al[r][c + 8];
                afl[mt][3] = *(const uint32_t*)&Al[r + 8][c + 8];
            }
            uint32_t bfh[8][2], bfl[8][2];
#pragma unroll
            for (int nt = 0; nt < 8; nt++) {
                int n = wn + nt * 8 + g;
                int c = kb + 2 * tg;
                bfh[nt][0] = *(const uint32_t*)&Bh[n][c];
                bfh[nt][1] = *(const uint32_t*)&Bh[n][c + 8];
                bfl[nt][0] = *(const uint32_t*)&Bl[n][c];
                bfl[nt][1] = *(const uint32_t*)&Bl[n][c + 8];
            }
#pragma unroll
            for (int mt = 0; mt < 2; mt++)
#pragma unroll
                for (int nt = 0; nt < 8; nt++) {
                    mma_bf16(acc[mt][nt], afh[mt], bfh[nt]);
                    mma_bf16(acc[mt][nt], afh[mt], bfl[nt]);
                    mma_bf16(acc[mt][nt], afl[mt], bfh[nt]);
                }
        }
    }

#pragma unroll
    for (int mt = 0; mt < 2; mt++) {
        int rbase = m0 + wm + mt * 16 + g;
#pragma unroll
        for (int nt = 0; nt < 8; nt++) {
            int cbase = n0 + wn + nt * 8 + 2 * tg;
            if (MODE == 0) {
                float* p0 = C + (size_t)rbase * GN + cbase;
                float* p1 = C + (size_t)(rbase + 8) * GN + cbase;
                p0[0] = acc[mt][nt][0];
                p0[1] = acc[mt][nt][1];
                p1[0] = acc[mt][nt][2];
                p1[1] = acc[mt][nt][3];
            } else {
                uint32_t h01, l01, h23, l23;
                split2(acc[mt][nt][0], acc[mt][nt][1], h01, l01);
                split2(acc[mt][nt][2], acc[mt][nt][3], h23, l23);
                *(uint32_t*)(Chi + (size_t)rbase * GN + cbase) = h01;
                *(uint32_t*)(Clo + (size_t)rbase * GN + cbase) = l01;
                *(uint32_t*)(Chi + (size_t)(rbase + 8) * GN + cbase) = h23;
                *(uint32_t*)(Clo + (size_t)(rbase + 8) * GN + cbase) = l23;
            }
        }
    }
}

// ===========================================================================
// HMMA flash attention. Block: 64 queries of one (b,h). 4 warps x 16 rows.
// Q/K/V arrive pre-split as bf16 hi/lo. S and O via m16n8k16 3-product split.
// Softmax exp on the FMA pipe. Masking identical to validated fp32 version.
// ===========================================================================
#define APAD 72  // bf16 elems per smem row (conflict-free frag loads)
#define SMEM_ATTN (6 * 64 * APAD * 2 + 64 * 4)

__global__ __launch_bounds__(128) void attn_mma(
    const __nv_bfloat16* __restrict__ Qh_, const __nv_bfloat16* __restrict__ Ql_,
    const __nv_bfloat16* __restrict__ Kh_, const __nv_bfloat16* __restrict__ Kl_,
    const __nv_bfloat16* __restrict__ Vh_, const __nv_bfloat16* __restrict__ Vl_,
    const int* __restrict__ maskg, float* __restrict__ Ctx) {
    extern __shared__ char smraw[];
    __nv_bfloat16* sQh = (__nv_bfloat16*)smraw;      // [64][APAD]
    __nv_bfloat16* sQl = sQh + 64 * APAD;
    __nv_bfloat16* sKh = sQl + 64 * APAD;
    __nv_bfloat16* sKl = sKh + 64 * APAD;
    __nv_bfloat16* sVh = sKl + 64 * APAD;            // transposed [dh][key]
    __nv_bfloat16* sVl = sVh + 64 * APAD;
    int* mks = (int*)(sVl + 64 * APAD);

    const int tid = threadIdx.x;
    const int wid = tid >> 5;
    const int lane = tid & 31;
    const int g = lane >> 2;
    const int tg = lane & 3;
    const int wm = wid * 16;
    const int q0 = blockIdx.x * 64;
    const int bh = blockIdx.y;
    const int b = bh >> 4;
    const int h = bh & 15;
    const size_t tokBase = (size_t)b * L_SEQ;
    const int colH = h * DH;

    // ---- load Q tile (hi/lo), 64 x 64 bf16 each
#pragma unroll
    for (int rep = 0; rep < 4; rep++) {
        int f = tid + rep * 128;
        int r = f >> 3;
        int cg = (f & 7) * 8;
        size_t gidx = (tokBase + q0 + r) * D_MODEL + colH + cg;
        *(uint4*)&sQh[r * APAD + cg] = *(const uint4*)(Qh_ + gidx);
        *(uint4*)&sQl[r * APAD + cg] = *(const uint4*)(Ql_ + gidx);
    }
    const int* mb = maskg + b * L_SEQ;
    const int mq0 = mb[q0 + wm + g];
    const int mq1 = mb[q0 + wm + g + 8];

    float m0 = -FLT_MAX, m1 = -FLT_MAX, l0 = 0.f, l1 = 0.f;
    float oacc[8][4];
#pragma unroll
    for (int i = 0; i < 8; i++)
#pragma unroll
        for (int j = 0; j < 4; j++) oacc[i][j] = 0.f;

    const float SCALE = 0.03125f;
    const float MASKV = -FLT_MAX * 0.03125f;

    for (int kt = 0; kt < L_SEQ / 64; kt++) {
        const int c0k = kt * 64;
        __syncthreads();
        // ---- K tile hi/lo: [key][dh]
#pragma unroll
        for (int rep = 0; rep < 4; rep++) {
            int f = tid + rep * 128;
            int r = f >> 3;
            int cg = (f & 7) * 8;
            size_t gidx = (tokBase + c0k + r) * D_MODEL + colH + cg;
            *(uint4*)&sKh[r * APAD + cg] = *(const uint4*)(Kh_ + gidx);
            *(uint4*)&sKl[r * APAD + cg] = *(const uint4*)(Kl_ + gidx);
        }
        // ---- V tile hi/lo transposed: [dh][key], key-pairs packed as bf162
#pragma unroll
        for (int rep = 0; rep < 2; rep++) {
            int f = tid + rep * 128;
            int p = f & 31;        // key pair
            int dg = (f >> 5) * 8; // dh group
            size_t g0i = (tokBase + c0k + 2 * p) * D_MODEL + colH + dg;
            size_t g1i = g0i + D_MODEL;
            uint4 a = *(const uint4*)(Vh_ + g0i);
            uint4 bb = *(const uint4*)(Vh_ + g1i);
            const __nv_bfloat16* pa = (const __nv_bfloat16*)&a;
            const __nv_bfloat16* pb = (const __nv_bfloat16*)&bb;
#pragma unroll
            for (int j = 0; j < 8; j++) {
                __nv_bfloat162 w; w.x = pa[j]; w.y = pb[j];
                *(uint32_t*)&sVh[(dg + j) * APAD + 2 * p] =
                    *reinterpret_cast<uint32_t*>(&w);
            }
            a = *(const uint4*)(Vl_ + g0i);
            bb = *(const uint4*)(Vl_ + g1i);
#pragma unroll
            for (int j = 0; j < 8; j++) {
                __nv_bfloat162 w; w.x = pa[j]; w.y = pb[j];
                *(uint32_t*)&sVl[(dg + j) * APAD + 2 * p] =
                    *reinterpret_cast<uint32_t*>(&w);
            }
        }
        if (tid < 64) mks[tid] = mb[c0k + tid];
        __syncthreads();

        // ---- S = Q K^T (3-product bf16 split)
        float sacc[8][4];
#pragma unroll
        for (int i = 0; i < 8; i++)
#pragma unroll
            for (int j = 0; j < 4; j++) sacc[i][j] = 0.f;

#pragma unroll
        for (int kk = 0; kk < 4; kk++) {
            const int c = kk * 16 + 2 * tg;
            const int r = wm + g;
            uint32_t aqh[4], aql[4];
            aqh[0] = *(const uint32_t*)&sQh[r * APAD + c];
            aqh[1] = *(const uint32_t*)&sQh[(r + 8) * APAD + c];
            aqh[2] = *(const uint32_t*)&sQh[r * APAD + c + 8];
            aqh[3] = *(const uint32_t*)&sQh[(r + 8) * APAD + c + 8];
            aql[0] = *(const uint32_t*)&sQl[r * APAD + c];
            aql[1] = *(const uint32_t*)&sQl[(r + 8) * APAD + c];
            aql[2] = *(const uint32_t*)&sQl[r * APAD + c + 8];
            aql[3] = *(const uint32_t*)&sQl[(r + 8) * APAD + c + 8];
#pragma unroll
            for (int nt = 0; nt < 8; nt++) {
                int n = nt * 8 + g;
                uint32_t bkh[2], bkl[2];
                bkh[0] = *(const uint32_t*)&sKh[n * APAD + c];
                bkh[1] = *(const uint32_t*)&sKh[n * APAD + c + 8];
                bkl[0] = *(const uint32_t*)&sKl[n * APAD + c];
                bkl[1] = *(const uint32_t*)&sKl[n * APAD + c + 8];
                mma_bf16(sacc[nt], aqh, bkh);
                mma_bf16(sacc[nt], aqh, bkl);
                mma_bf16(sacc[nt], aql, bkh);
            }
        }

        // ---- mask + scale (exactly the validated semantics)
#pragma unroll
        for (int nt = 0; nt < 8; nt++) {
            int mkA = mks[nt * 8 + 2 * tg];
            int mkB = mks[nt * 8 + 2 * tg + 1];
            sacc[nt][0] = (mq0 && mkA) ? sacc[nt][0] * SCALE : MASKV;
            sacc[nt][1] = (mq0 && mkB) ? sacc[nt][1] * SCALE : MASKV;
            sacc[nt][2] = (mq1 && mkA) ? sacc[nt][2] * SCALE : MASKV;
            sacc[nt][3] = (mq1 && mkB) ? sacc[nt][3] * SCALE : MASKV;
        }

        // ---- online softmax (rows g and g+8), quad shfl reduction
        float rx0 = -FLT_MAX, rx1 = -FLT_MAX;
#pragma unroll
        for (int nt = 0; nt < 8; nt++) {
            rx0 = fmaxf(rx0, fmaxf(sacc[nt][0], sacc[nt][1]));
            rx1 = fmaxf(rx1, fmaxf(sacc[nt][2], sacc[nt][3]));
        }
        rx0 = fmaxf(rx0, __shfl_xor_sync(0xffffffffu, rx0, 1));
        rx0 = fmaxf(rx0, __shfl_xor_sync(0xffffffffu, rx0, 2));
        rx1 = fmaxf(rx1, __shfl_xor_sync(0xffffffffu, rx1, 1));
        rx1 = fmaxf(rx1, __shfl_xor_sync(0xffffffffu, rx1, 2));

        float mn0 = fmaxf(m0, rx0);
        float mn1 = fmaxf(m1, rx1);
        float corr0 = fexp(m0 - mn0);
        float corr1 = fexp(m1 - mn1);
        float s0 = 0.f, s1 = 0.f;
#pragma unroll
        for (int nt = 0; nt < 8; nt++) {
            sacc[nt][0] = fexp(sacc[nt][0] - mn0);
            sacc[nt][1] = fexp(sacc[nt][1] - mn0);
            sacc[nt][2] = fexp(sacc[nt][2] - mn1);
            sacc[nt][3] = fexp(sacc[nt][3] - mn1);
            s0 += sacc[nt][0] + sacc[nt][1];
            s1 += sacc[nt][2] + sacc[nt][3];
        }
        s0 += __shfl_xor_sync(0xffffffffu, s0, 1);
        s0 += __shfl_xor_sync(0xffffffffu, s0, 2);
        s1 += __shfl_xor_sync(0xffffffffu, s1, 1);
        s1 += __shfl_xor_sync(0xffffffffu, s1, 2);
        l0 = l0 * corr0 + s0;
        l1 = l1 * corr1 + s1;
        m0 = mn0;
        m1 = mn1;
#pragma unroll
        for (int nto = 0; nto < 8; nto++) {
            oacc[nto][0] *= corr0;
            oacc[nto][1] *= corr0;
            oacc[nto][2] *= corr1;
            oacc[nto][3] *= corr1;
        }

        // ---- O += P V  (P A-frags come straight from sacc, no smem trip)
#pragma unroll
        for (int kk = 0; kk < 4; kk++) {
            uint32_t aph[4], apl[4];
            split2(sacc[2 * kk][0], sacc[2 * kk][1], aph[0], apl[0]);
            split2(sacc[2 * kk][2], sacc[2 * kk][3], aph[1], apl[1]);
            split2(sacc[2 * kk + 1][0], sacc[2 * kk + 1][1], aph[2], apl[2]);
            split2(sacc[2 * kk + 1][2], sacc[2 * kk + 1][3], aph[3], apl[3]);
            const int c = kk * 16 + 2 * tg;
#pragma unroll
            for (int nto = 0; nto < 8; nto++) {
                int n = nto * 8 + g;
                uint32_t bvh[2], bvl[2];
                bvh[0] = *(const uint32_t*)&sVh[n * APAD + c];
                bvh[1] = *(const uint32_t*)&sVh[n * APAD + c + 8];
                bvl[0] = *(const uint32_t*)&sVl[n * APAD + c];
                bvl[1] = *(const uint32_t*)&sVl[n * APAD + c + 8];
                mma_bf16(oacc[nto], aph, bvh);
                mma_bf16(oacc[nto], aph, bvl);
                mma_bf16(oacc[nto], apl, bvh);
            }
        }
    }

    // ---- epilogue: normalize, write ctx fp32 [token][h*64+d]
    const float inv0 = 1.0f / l0;
    const float inv1 = 1.0f / l1;
    const size_t r0 = (tokBase + q0 + wm + g) * D_MODEL;
    const size_t r1 = r0 + 8 * D_MODEL;
#pragma unroll
    for (int nto = 0; nto < 8; nto++) {
        int cb = colH + nto * 8 + 2 * tg;
        *(float2*)(Ctx + r0 + cb) =
            make_float2(oacc[nto][0] * inv0, oacc[nto][1] * inv0);
        *(float2*)(Ctx + r1 + cb) =
            make_float2(oacc[nto][2] * inv1, oacc[nto][3] * inv1);
    }
}

// ---------------------------------------------------------------------------
extern "C" void kernel_launch(void* const* d_in, const int* in_sizes, int n_in,
                              void* d_out, int out_size) {
    const float* x = (const float*)d_in[0];
    const int* mask = (const int*)d_in[1];
    const float* wq = (const float*)d_in[2];
    const float* wk = (const float*)d_in[3];
    const float* wv = (const float*)d_in[4];
    const float* wo = (const float*)d_in[5];
    float* out = (float*)d_out;

    __nv_bfloat16 *qh, *ql, *kh, *kl, *vh, *vl;
    float* c;
    cudaGetSymbolAddress((void**)&qh, g_qh);
    cudaGetSymbolAddress((void**)&ql, g_ql);
    cudaGetSymbolAddress((void**)&kh, g_kh);
    cudaGetSymbolAddress((void**)&kl, g_kl);
    cudaGetSymbolAddress((void**)&vh, g_vh);
    cudaGetSymbolAddress((void**)&vl, g_vl);
    cudaGetSymbolAddress((void**)&c, g_c);

    cudaFuncSetAttribute(attn_mma, cudaFuncAttributeMaxDynamicSharedMemorySize,
                         SMEM_ATTN);

    dim3 gg(GN / 128, M_TOK / 128);  // (8, 32)
    gemm_mma<1><<<gg, 256>>>(x, wq, nullptr, qh, ql);
    gemm_mma<1><<<gg, 256>>>(x, wk, nullptr, kh, kl);
    gemm_mma<1><<<gg, 256>>>(x, wv, nullptr, vh, vl);

    attn_mma<<<dim3(L_SEQ / 64, NB * NH), 128, SMEM_ATTN>>>(qh, ql, kh, kl, vh,
                                                            vl, mask, c);

    gemm_mma<0><<<gg, 256>>>(c, wo, out, nullptr, nullptr);
}

// round 7
// speedup vs baseline: 2.0975x; 1.5421x over previous
#include <cuda_runtime.h>
#include <cuda_bf16.h>
#include <math.h>
#include <float.h>
#include <stdint.h>

#define L_SEQ 2048
#define D_MODEL 1024
#define NH 16
#define DH 64
#define NB 2
#define M_TOK (NB * L_SEQ)  // 4096
#define GK 1024
#define GN 1024

// Scratch (__device__ globals; allocation-free rule)
__device__ __nv_bfloat16 g_xh[(size_t)M_TOK * D_MODEL];
__device__ __nv_bfloat16 g_xl[(size_t)M_TOK * D_MODEL];
__device__ __nv_bfloat16 g_qh[(size_t)M_TOK * D_MODEL];
__device__ __nv_bfloat16 g_ql[(size_t)M_TOK * D_MODEL];
__device__ __nv_bfloat16 g_kh[(size_t)M_TOK * D_MODEL];
__device__ __nv_bfloat16 g_kl[(size_t)M_TOK * D_MODEL];
__device__ __nv_bfloat16 g_vh[(size_t)M_TOK * D_MODEL];
__device__ __nv_bfloat16 g_vl[(size_t)M_TOK * D_MODEL];
__device__ __nv_bfloat16 g_ch[(size_t)M_TOK * D_MODEL];
__device__ __nv_bfloat16 g_cl[(size_t)M_TOK * D_MODEL];
__device__ __nv_bfloat16 g_wTh[4 * (size_t)GK * GN];  // transposed [n][k]
__device__ __nv_bfloat16 g_wTl[4 * (size_t)GK * GN];

// ===========================================================================
// common helpers
// ===========================================================================
__device__ __forceinline__ void mma_bf16(float* c, const uint32_t* a,
                                         const uint32_t* b) {
    asm volatile(
        "mma.sync.aligned.m16n8k16.row.col.f32.bf16.bf16.f32 "
        "{%0,%1,%2,%3}, {%4,%5,%6,%7}, {%8,%9}, {%0,%1,%2,%3};"
        : "+f"(c[0]), "+f"(c[1]), "+f"(c[2]), "+f"(c[3])
        : "r"(a[0]), "r"(a[1]), "r"(a[2]), "r"(a[3]), "r"(b[0]), "r"(b[1]));
}
__device__ __forceinline__ uint32_t pack2bf(float a, float b) {
    __nv_bfloat162 h = __floats2bfloat162_rn(a, b);
    return *reinterpret_cast<uint32_t*>(&h);
}
__device__ __forceinline__ void split2(float x, float y, uint32_t& hi,
                                       uint32_t& lo) {
    __nv_bfloat16 hx = __float2bfloat16(x);
    __nv_bfloat16 hy = __float2bfloat16(y);
    __nv_bfloat162 hp;
    hp.x = hx; hp.y = hy;
    hi = *reinterpret_cast<uint32_t*>(&hp);
    lo = pack2bf(x - __bfloat162float(hx), y - __bfloat162float(hy));
}
// exp on the FMA pipe. Exact 1.0 at x==0; safe for -FLT_MAX inputs.
__device__ __forceinline__ float fexp(float x) {
    float y = x * 1.4426950408889634f;
    y = fmaxf(y, -126.0f);
    float n = rintf(y);
    float f = y - n;
    float t = f * 0.6931471805599453f;
    float p = 1.9841270e-4f;
    p = fmaf(p, t, 1.3888889e-3f);
    p = fmaf(p, t, 8.3333333e-3f);
    p = fmaf(p, t, 4.1666668e-2f);
    p = fmaf(p, t, 0.16666667f);
    p = fmaf(p, t, 0.5f);
    p = fmaf(p, t, 1.0f);
    p = fmaf(p, t, 1.0f);
    return __int_as_float(__float_as_int(p) + ((int)n << 23));
}
__device__ __forceinline__ void cp16(uint32_t s, const void* g) {
    asm volatile("cp.async.cg.shared.global [%0], [%1], 16;" :: "r"(s), "l"(g));
}

// ===========================================================================
// one-shot split kernels
// ===========================================================================
__global__ __launch_bounds__(256) void splitV(const float* __restrict__ in,
                                              __nv_bfloat16* __restrict__ hi,
                                              __nv_bfloat16* __restrict__ lo) {
    int i = blockIdx.x * 256 + threadIdx.x;
    float4 v = ((const float4*)in)[i];
    uint32_t h01, l01, h23, l23;
    split2(v.x, v.y, h01, l01);
    split2(v.z, v.w, h23, l23);
    ((uint2*)hi)[i] = make_uint2(h01, h23);
    ((uint2*)lo)[i] = make_uint2(l01, l23);
}
// W [k][n] fp32 -> WT [n][k] bf16 hi/lo
__global__ __launch_bounds__(256) void splitT(const float* __restrict__ W,
                                              __nv_bfloat16* __restrict__ WhT,
                                              __nv_bfloat16* __restrict__ WlT) {
    __shared__ float t[32][33];
    const int n0 = blockIdx.x * 32, k0 = blockIdx.y * 32;
    const int tx = threadIdx.x & 31, ty = threadIdx.x >> 5;  // 32x8
#pragma unroll
    for (int r = ty; r < 32; r += 8)
        t[r][tx] = W[(size_t)(k0 + r) * GN + n0 + tx];
    __syncthreads();
#pragma unroll
    for (int r = ty; r < 32; r += 8) {
        float v = t[tx][r];  // = W[k0+tx][n0+r]
        __nv_bfloat16 h = __float2bfloat16(v);
        WhT[(size_t)(n0 + r) * GK + k0 + tx] = h;
        WlT[(size_t)(n0 + r) * GK + k0 + tx] =
            __float2bfloat16(v - __bfloat162float(h));
    }
}

// ===========================================================================
// bf16 split GEMM, cp.async double-buffered.
// A: [M][K] bf16 hi/lo.  B: [N][K] bf16 hi/lo (pre-transposed).
// MODE 0: fp32 C.  MODE 1: bf16 hi/lo C.
// Block 128x128, k-tile 32, 8 warps 4(m)x2(n).
// ===========================================================================
#define BKT 32
#define KT (GK / BKT)  // 32
#define KPAD 40
#define TILE_E (128 * KPAD)       // bf16 elems per tile
#define TILE_BY (TILE_E * 2)      // bytes per tile
#define GEMM_SMEM (8 * TILE_BY)   // 81920 B

template <int MODE>
__global__ __launch_bounds__(256) void gemm_bf(
    const __nv_bfloat16* __restrict__ Ahg, const __nv_bfloat16* __restrict__ Alg,
    const __nv_bfloat16* __restrict__ BhT, const __nv_bfloat16* __restrict__ BlT,
    float* __restrict__ C, __nv_bfloat16* __restrict__ Chi,
    __nv_bfloat16* __restrict__ Clo) {
    extern __shared__ __nv_bfloat16 dsm[];
    const uint32_t sbase = (uint32_t)__cvta_generic_to_shared(dsm);

    const int tid = threadIdx.x;
    const int wid = tid >> 5;
    const int lane = tid & 31;
    const int g = lane >> 2;
    const int tg = lane & 3;
    const int wm = (wid & 3) * 32;
    const int wn = (wid >> 2) * 64;
    const int m0 = blockIdx.y * 128;
    const int n0 = blockIdx.x * 128;

    // cp.async mapping: each thread: rows r0, r0+64; 16B chunk c (of 4)
    const int r0 = tid >> 2;
    const int ck = (tid & 3) * 8;  // bf16 col offset of the 16B chunk
    const uint32_t so0 = (uint32_t)(r0 * KPAD + ck) * 2;
    const uint32_t so1 = (uint32_t)((r0 + 64) * KPAD + ck) * 2;

    float acc[2][8][4];
#pragma unroll
    for (int i = 0; i < 2; i++)
#pragma unroll
        for (int j = 0; j < 8; j++)
#pragma unroll
            for (int r = 0; r < 4; r++) acc[i][j][r] = 0.f;

    auto issue = [&](int t, int st) {
        const int k0 = t * BKT;
        const uint32_t b = sbase + (uint32_t)st * 4 * TILE_BY;
        size_t gA0 = (size_t)(m0 + r0) * GK + k0 + ck;
        size_t gA1 = gA0 + (size_t)64 * GK;
        size_t gB0 = (size_t)(n0 + r0) * GK + k0 + ck;
        size_t gB1 = gB0 + (size_t)64 * GK;
        cp16(b + so0, Ahg + gA0);
        cp16(b + so1, Ahg + gA1);
        cp16(b + TILE_BY + so0, Alg + gA0);
        cp16(b + TILE_BY + so1, Alg + gA1);
        cp16(b + 2 * TILE_BY + so0, BhT + gB0);
        cp16(b + 2 * TILE_BY + so1, BhT + gB1);
        cp16(b + 3 * TILE_BY + so0, BlT + gB0);
        cp16(b + 3 * TILE_BY + so1, BlT + gB1);
    };

    issue(0, 0);
    asm volatile("cp.async.commit_group;" ::: "memory");

    for (int t = 0; t < KT; t++) {
        const int st = t & 1;
        if (t + 1 < KT) {
            issue(t + 1, st ^ 1);
            asm volatile("cp.async.commit_group;" ::: "memory");
            asm volatile("cp.async.wait_group 1;" ::: "memory");
        } else {
            asm volatile("cp.async.wait_group 0;" ::: "memory");
        }
        __syncthreads();

        const __nv_bfloat16* sAh = dsm + (size_t)st * 4 * TILE_E;
        const __nv_bfloat16* sAl = sAh + TILE_E;
        const __nv_bfloat16* sBh = sAl + TILE_E;
        const __nv_bfloat16* sBl = sBh + TILE_E;

#pragma unroll
        for (int kh = 0; kh < 2; kh++) {
            const int kb = kh * 16;
            const int c = kb + 2 * tg;
            uint32_t afh[2][4], afl[2][4];
#pragma unroll
            for (int mt = 0; mt < 2; mt++) {
                int r = wm + mt * 16 + g;
                afh[mt][0] = *(const uint32_t*)&sAh[r * KPAD + c];
                afh[mt][1] = *(const uint32_t*)&sAh[(r + 8) * KPAD + c];
                afh[mt][2] = *(const uint32_t*)&sAh[r * KPAD + c + 8];
                afh[mt][3] = *(const uint32_t*)&sAh[(r + 8) * KPAD + c + 8];
                afl[mt][0] = *(const uint32_t*)&sAl[r * KPAD + c];
                afl[mt][1] = *(const uint32_t*)&sAl[(r + 8) * KPAD + c];
                afl[mt][2] = *(const uint32_t*)&sAl[r * KPAD + c + 8];
                afl[mt][3] = *(const uint32_t*)&sAl[(r + 8) * KPAD + c + 8];
            }
            uint32_t bfh[8][2], bfl[8][2];
#pragma unroll
            for (int nt = 0; nt < 8; nt++) {
                int n = wn + nt * 8 + g;
                bfh[nt][0] = *(const uint32_t*)&sBh[n * KPAD + c];
                bfh[nt][1] = *(const uint32_t*)&sBh[n * KPAD + c + 8];
                bfl[nt][0] = *(const uint32_t*)&sBl[n * KPAD + c];
                bfl[nt][1] = *(const uint32_t*)&sBl[n * KPAD + c + 8];
            }
#pragma unroll
            for (int mt = 0; mt < 2; mt++)
#pragma unroll
                for (int nt = 0; nt < 8; nt++) {
                    mma_bf16(acc[mt][nt], afh[mt], bfh[nt]);
                    mma_bf16(acc[mt][nt], afh[mt], bfl[nt]);
                    mma_bf16(acc[mt][nt], afl[mt], bfh[nt]);
                }
        }
        __syncthreads();
    }

#pragma unroll
    for (int mt = 0; mt < 2; mt++) {
        int rbase = m0 + wm + mt * 16 + g;
#pragma unroll
        for (int nt = 0; nt < 8; nt++) {
            int cbase = n0 + wn + nt * 8 + 2 * tg;
            if (MODE == 0) {
                float* p0 = C + (size_t)rbase * GN + cbase;
                float* p1 = C + (size_t)(rbase + 8) * GN + cbase;
                p0[0] = acc[mt][nt][0];
                p0[1] = acc[mt][nt][1];
                p1[0] = acc[mt][nt][2];
                p1[1] = acc[mt][nt][3];
            } else {
                uint32_t h01, l01, h23, l23;
                split2(acc[mt][nt][0], acc[mt][nt][1], h01, l01);
                split2(acc[mt][nt][2], acc[mt][nt][3], h23, l23);
                *(uint32_t*)(Chi + (size_t)rbase * GN + cbase) = h01;
                *(uint32_t*)(Clo + (size_t)rbase * GN + cbase) = l01;
                *(uint32_t*)(Chi + (size_t)(rbase + 8) * GN + cbase) = h23;
                *(uint32_t*)(Clo + (size_t)(rbase + 8) * GN + cbase) = l23;
            }
        }
    }
}

// ===========================================================================
// HMMA flash attention (R5 kernel; epilogue now emits bf16 hi/lo ctx).
// ===========================================================================
#define APAD 72
#define SMEM_ATTN (6 * 64 * APAD * 2 + 64 * 4)

__global__ __launch_bounds__(128) void attn_mma(
    const __nv_bfloat16* __restrict__ Qh_, const __nv_bfloat16* __restrict__ Ql_,
    const __nv_bfloat16* __restrict__ Kh_, const __nv_bfloat16* __restrict__ Kl_,
    const __nv_bfloat16* __restrict__ Vh_, const __nv_bfloat16* __restrict__ Vl_,
    const int* __restrict__ maskg, __nv_bfloat16* __restrict__ Ch,
    __nv_bfloat16* __restrict__ Cl) {
    extern __shared__ char smraw[];
    __nv_bfloat16* sQh = (__nv_bfloat16*)smraw;
    __nv_bfloat16* sQl = sQh + 64 * APAD;
    __nv_bfloat16* sKh = sQl + 64 * APAD;
    __nv_bfloat16* sKl = sKh + 64 * APAD;
    __nv_bfloat16* sVh = sKl + 64 * APAD;
    __nv_bfloat16* sVl = sVh + 64 * APAD;
    int* mks = (int*)(sVl + 64 * APAD);

    const int tid = threadIdx.x;
    const int wid = tid >> 5;
    const int lane = tid & 31;
    const int g = lane >> 2;
    const int tg = lane & 3;
    const int wm = wid * 16;
    const int q0 = blockIdx.x * 64;
    const int bh = blockIdx.y;
    const int b = bh >> 4;
    const int h = bh & 15;
    const size_t tokBase = (size_t)b * L_SEQ;
    const int colH = h * DH;

#pragma unroll
    for (int rep = 0; rep < 4; rep++) {
        int f = tid + rep * 128;
        int r = f >> 3;
        int cg = (f & 7) * 8;
        size_t gidx = (tokBase + q0 + r) * D_MODEL + colH + cg;
        *(uint4*)&sQh[r * APAD + cg] = *(const uint4*)(Qh_ + gidx);
        *(uint4*)&sQl[r * APAD + cg] = *(const uint4*)(Ql_ + gidx);
    }
    const int* mb = maskg + b * L_SEQ;
    const int mq0 = mb[q0 + wm + g];
    const int mq1 = mb[q0 + wm + g + 8];

    float m0 = -FLT_MAX, m1 = -FLT_MAX, l0 = 0.f, l1 = 0.f;
    float oacc[8][4];
#pragma unroll
    for (int i = 0; i < 8; i++)
#pragma unroll
        for (int j = 0; j < 4; j++) oacc[i][j] = 0.f;

    const float SCALE = 0.03125f;
    const float MASKV = -FLT_MAX * 0.03125f;

    for (int kt = 0; kt < L_SEQ / 64; kt++) {
        const int c0k = kt * 64;
        __syncthreads();
#pragma unroll
        for (int rep = 0; rep < 4; rep++) {
            int f = tid + rep * 128;
            int r = f >> 3;
            int cg = (f & 7) * 8;
            size_t gidx = (tokBase + c0k + r) * D_MODEL + colH + cg;
            *(uint4*)&sKh[r * APAD + cg] = *(const uint4*)(Kh_ + gidx);
            *(uint4*)&sKl[r * APAD + cg] = *(const uint4*)(Kl_ + gidx);
        }
#pragma unroll
        for (int rep = 0; rep < 2; rep++) {
            int f = tid + rep * 128;
            int p = f & 31;
            int dg = (f >> 5) * 8;
            size_t g0i = (tokBase + c0k + 2 * p) * D_MODEL + colH + dg;
            size_t g1i = g0i + D_MODEL;
            {
                uint4 a = *(const uint4*)(Vh_ + g0i);
                uint4 bb = *(const uint4*)(Vh_ + g1i);
                const __nv_bfloat16* pa = (const __nv_bfloat16*)&a;
                const __nv_bfloat16* pb = (const __nv_bfloat16*)&bb;
#pragma unroll
                for (int j = 0; j < 8; j++) {
                    __nv_bfloat162 w; w.x = pa[j]; w.y = pb[j];
                    *(uint32_t*)&sVh[(dg + j) * APAD + 2 * p] =
                        *reinterpret_cast<uint32_t*>(&w);
                }
            }
            {
                uint4 a = *(const uint4*)(Vl_ + g0i);
                uint4 bb = *(const uint4*)(Vl_ + g1i);
                const __nv_bfloat16* pa = (const __nv_bfloat16*)&a;
                const __nv_bfloat16* pb = (const __nv_bfloat16*)&bb;
#pragma unroll
                for (int j = 0; j < 8; j++) {
                    __nv_bfloat162 w; w.x = pa[j]; w.y = pb[j];
                    *(uint32_t*)&sVl[(dg + j) * APAD + 2 * p] =
                        *reinterpret_cast<uint32_t*>(&w);
                }
            }
        }
        if (tid < 64) mks[tid] = mb[c0k + tid];
        __syncthreads();

        float sacc[8][4];
#pragma unroll
        for (int i = 0; i < 8; i++)
#pragma unroll
            for (int j = 0; j < 4; j++) sacc[i][j] = 0.f;

#pragma unroll
        for (int kk = 0; kk < 4; kk++) {
            const int c = kk * 16 + 2 * tg;
            const int r = wm + g;
            uint32_t aqh[4], aql[4];
            aqh[0] = *(const uint32_t*)&sQh[r * APAD + c];
            aqh[1] = *(const uint32_t*)&sQh[(r + 8) * APAD + c];
            aqh[2] = *(const uint32_t*)&sQh[r * APAD + c + 8];
            aqh[3] = *(const uint32_t*)&sQh[(r + 8) * APAD + c + 8];
            aql[0] = *(const uint32_t*)&sQl[r * APAD + c];
            aql[1] = *(const uint32_t*)&sQl[(r + 8) * APAD + c];
            aql[2] = *(const uint32_t*)&sQl[r * APAD + c + 8];
            aql[3] = *(const uint32_t*)&sQl[(r + 8) * APAD + c + 8];
#pragma unroll
            for (int nt = 0; nt < 8; nt++) {
                int n = nt * 8 + g;
                uint32_t bkh[2], bkl[2];
                bkh[0] = *(const uint32_t*)&sKh[n * APAD + c];
                bkh[1] = *(const uint32_t*)&sKh[n * APAD + c + 8];
                bkl[0] = *(const uint32_t*)&sKl[n * APAD + c];
                bkl[1] = *(const uint32_t*)&sKl[n * APAD + c + 8];
                mma_bf16(sacc[nt], aqh, bkh);
                mma_bf16(sacc[nt], aqh, bkl);
                mma_bf16(sacc[nt], aql, bkh);
            }
        }

#pragma unroll
        for (int nt = 0; nt < 8; nt++) {
            int mkA = mks[nt * 8 + 2 * tg];
            int mkB = mks[nt * 8 + 2 * tg + 1];
            sacc[nt][0] = (mq0 && mkA) ? sacc[nt][0] * SCALE : MASKV;
            sacc[nt][1] = (mq0 && mkB) ? sacc[nt][1] * SCALE : MASKV;
            sacc[nt][2] = (mq1 && mkA) ? sacc[nt][2] * SCALE : MASKV;
            sacc[nt][3] = (mq1 && mkB) ? sacc[nt][3] * SCALE : MASKV;
        }

        float rx0 = -FLT_MAX, rx1 = -FLT_MAX;
#pragma unroll
        for (int nt = 0; nt < 8; nt++) {
            rx0 = fmaxf(rx0, fmaxf(sacc[nt][0], sacc[nt][1]));
            rx1 = fmaxf(rx1, fmaxf(sacc[nt][2], sacc[nt][3]));
        }
        rx0 = fmaxf(rx0, __shfl_xor_sync(0xffffffffu, rx0, 1));
        rx0 = fmaxf(rx0, __shfl_xor_sync(0xffffffffu, rx0, 2));
        rx1 = fmaxf(rx1, __shfl_xor_sync(0xffffffffu, rx1, 1));
        rx1 = fmaxf(rx1, __shfl_xor_sync(0xffffffffu, rx1, 2));

        float mn0 = fmaxf(m0, rx0);
        float mn1 = fmaxf(m1, rx1);
        float corr0 = fexp(m0 - mn0);
        float corr1 = fexp(m1 - mn1);
        float s0 = 0.f, s1 = 0.f;
#pragma unroll
        for (int nt = 0; nt < 8; nt++) {
            sacc[nt][0] = fexp(sacc[nt][0] - mn0);
            sacc[nt][1] = fexp(sacc[nt][1] - mn0);
            sacc[nt][2] = fexp(sacc[nt][2] - mn1);
            sacc[nt][3] = fexp(sacc[nt][3] - mn1);
            s0 += sacc[nt][0] + sacc[nt][1];
            s1 += sacc[nt][2] + sacc[nt][3];
        }
        s0 += __shfl_xor_sync(0xffffffffu, s0, 1);
        s0 += __shfl_xor_sync(0xffffffffu, s0, 2);
        s1 += __shfl_xor_sync(0xffffffffu, s1, 1);
        s1 += __shfl_xor_sync(0xffffffffu, s1, 2);
        l0 = l0 * corr0 + s0;
        l1 = l1 * corr1 + s1;
        m0 = mn0;
        m1 = mn1;
#pragma unroll
        for (int nto = 0; nto < 8; nto++) {
            oacc[nto][0] *= corr0;
            oacc[nto][1] *= corr0;
            oacc[nto][2] *= corr1;
            oacc[nto][3] *= corr1;
        }

#pragma unroll
        for (int kk = 0; kk < 4; kk++) {
            uint32_t aph[4], apl[4];
            split2(sacc[2 * kk][0], sacc[2 * kk][1], aph[0], apl[0]);
            split2(sacc[2 * kk][2], sacc[2 * kk][3], aph[1], apl[1]);
            split2(sacc[2 * kk + 1][0], sacc[2 * kk + 1][1], aph[2], apl[2]);
            split2(sacc[2 * kk + 1][2], sacc[2 * kk + 1][3], aph[3], apl[3]);
            const int c = kk * 16 + 2 * tg;
#pragma unroll
            for (int nto = 0; nto < 8; nto++) {
                int n = nto * 8 + g;
                uint32_t bvh[2], bvl[2];
                bvh[0] = *(const uint32_t*)&sVh[n * APAD + c];
                bvh[1] = *(const uint32_t*)&sVh[n * APAD + c + 8];
                bvl[0] = *(const uint32_t*)&sVl[n * APAD + c];
                bvl[1] = *(const uint32_t*)&sVl[n * APAD + c + 8];
                mma_bf16(oacc[nto], aph, bvh);
                mma_bf16(oacc[nto], aph, bvl);
                mma_bf16(oacc[nto], apl, bvh);
            }
        }
    }

    // epilogue: normalize + split to bf16 hi/lo ctx
    const float inv0 = 1.0f / l0;
    const float inv1 = 1.0f / l1;
    const size_t r0 = (tokBase + q0 + wm + g) * D_MODEL;
    const size_t r1 = r0 + 8 * D_MODEL;
#pragma unroll
    for (int nto = 0; nto < 8; nto++) {
        int cb = colH + nto * 8 + 2 * tg;
        uint32_t h01, l01, h23, l23;
        split2(oacc[nto][0] * inv0, oacc[nto][1] * inv0, h01, l01);
        split2(oacc[nto][2] * inv1, oacc[nto][3] * inv1, h23, l23);
        *(uint32_t*)(Ch + r0 + cb) = h01;
        *(uint32_t*)(Cl + r0 + cb) = l01;
        *(uint32_t*)(Ch + r1 + cb) = h23;
        *(uint32_t*)(Cl + r1 + cb) = l23;
    }
}

// ---------------------------------------------------------------------------
extern "C" void kernel_launch(void* const* d_in, const int* in_sizes, int n_in,
                              void* d_out, int out_size) {
    const float* x = (const float*)d_in[0];
    const int* mask = (const int*)d_in[1];
    const float* w[4] = {(const float*)d_in[2], (const float*)d_in[3],
                         (const float*)d_in[4], (const float*)d_in[5]};
    float* out = (float*)d_out;

    __nv_bfloat16 *xh, *xl, *qh, *ql, *kh, *kl, *vh, *vl, *ch, *cl, *wTh, *wTl;
    cudaGetSymbolAddress((void**)&xh, g_xh);
    cudaGetSymbolAddress((void**)&xl, g_xl);
    cudaGetSymbolAddress((void**)&qh, g_qh);
    cudaGetSymbolAddress((void**)&ql, g_ql);
    cudaGetSymbolAddress((void**)&kh, g_kh);
    cudaGetSymbolAddress((void**)&kl, g_kl);
    cudaGetSymbolAddress((void**)&vh, g_vh);
    cudaGetSymbolAddress((void**)&vl, g_vl);
    cudaGetSymbolAddress((void**)&ch, g_ch);
    cudaGetSymbolAddress((void**)&cl, g_cl);
    cudaGetSymbolAddress((void**)&wTh, g_wTh);
    cudaGetSymbolAddress((void**)&wTl, g_wTl);

    cudaFuncSetAttribute(attn_mma, cudaFuncAttributeMaxDynamicSharedMemorySize,
                         SMEM_ATTN);
    cudaFuncSetAttribute(gemm_bf<0>,
                         cudaFuncAttributeMaxDynamicSharedMemorySize, GEMM_SMEM);
    cudaFuncSetAttribute(gemm_bf<1>,
                         cudaFuncAttributeMaxDynamicSharedMemorySize, GEMM_SMEM);

    // 1) split inputs
    splitV<<<(M_TOK * D_MODEL / 4) / 256, 256>>>(x, xh, xl);
    for (int i = 0; i < 4; i++)
        splitT<<<dim3(GN / 32, GK / 32), 256>>>(w[i], wTh + (size_t)i * GK * GN,
                                                wTl + (size_t)i * GK * GN);

    // 2) QKV projections
    dim3 gg(GN / 128, M_TOK / 128);
    gemm_bf<1><<<gg, 256, GEMM_SMEM>>>(xh, xl, wTh + 0 * (size_t)GK * GN,
                                       wTl + 0 * (size_t)GK * GN, nullptr, qh, ql);
    gemm_bf<1><<<gg, 256, GEMM_SMEM>>>(xh, xl, wTh + 1 * (size_t)GK * GN,
                                       wTl + 1 * (size_t)GK * GN, nullptr, kh, kl);
    gemm_bf<1><<<gg, 256, GEMM_SMEM>>>(xh, xl, wTh + 2 * (size_t)GK * GN,
                                       wTl + 2 * (size_t)GK * GN, nullptr, vh, vl);

    // 3) attention
    attn_mma<<<dim3(L_SEQ / 64, NB * NH), 128, SMEM_ATTN>>>(qh, ql, kh, kl, vh,
                                                            vl, mask, ch, cl);

    // 4) output projection
    gemm_bf<0><<<gg, 256, GEMM_SMEM>>>(ch, cl, wTh + 3 * (size_t)GK * GN,
                                       wTl + 3 * (size_t)GK * GN, out, nullptr,
                                       nullptr);
}

// round 8
// speedup vs baseline: 2.4537x; 1.1698x over previous
#include <cuda_runtime.h>
#include <cuda_bf16.h>
#include <math.h>
#include <float.h>
#include <stdint.h>

#define L_SEQ 2048
#define D_MODEL 1024
#define NH 16
#define DH 64
#define NB 2
#define M_TOK (NB * L_SEQ)  // 4096
#define GK 1024
#define GN 1024

// Scratch (__device__ globals; allocation-free rule)
__device__ __nv_bfloat16 g_xh[(size_t)M_TOK * D_MODEL];
__device__ __nv_bfloat16 g_xl[(size_t)M_TOK * D_MODEL];
__device__ __nv_bfloat16 g_qh[(size_t)M_TOK * D_MODEL];
__device__ __nv_bfloat16 g_ql[(size_t)M_TOK * D_MODEL];
__device__ __nv_bfloat16 g_kh[(size_t)M_TOK * D_MODEL];
__device__ __nv_bfloat16 g_kl[(size_t)M_TOK * D_MODEL];
__device__ __nv_bfloat16 g_vh[(size_t)M_TOK * D_MODEL];
__device__ __nv_bfloat16 g_vl[(size_t)M_TOK * D_MODEL];
__device__ __nv_bfloat16 g_ch[(size_t)M_TOK * D_MODEL];
__device__ __nv_bfloat16 g_cl[(size_t)M_TOK * D_MODEL];
__device__ __nv_bfloat16 g_wTh[4 * (size_t)GK * GN];  // transposed [n][k]
__device__ __nv_bfloat16 g_wTl[4 * (size_t)GK * GN];

// ===========================================================================
// common helpers
// ===========================================================================
__device__ __forceinline__ void mma_bf16(float* c, const uint32_t* a,
                                         const uint32_t* b) {
    asm volatile(
        "mma.sync.aligned.m16n8k16.row.col.f32.bf16.bf16.f32 "
        "{%0,%1,%2,%3}, {%4,%5,%6,%7}, {%8,%9}, {%0,%1,%2,%3};"
        : "+f"(c[0]), "+f"(c[1]), "+f"(c[2]), "+f"(c[3])
        : "r"(a[0]), "r"(a[1]), "r"(a[2]), "r"(a[3]), "r"(b[0]), "r"(b[1]));
}
__device__ __forceinline__ void ldm_x4(uint32_t* r, uint32_t addr) {
    asm volatile(
        "ldmatrix.sync.aligned.m8n8.x4.shared.b16 {%0,%1,%2,%3}, [%4];"
        : "=r"(r[0]), "=r"(r[1]), "=r"(r[2]), "=r"(r[3]) : "r"(addr));
}
__device__ __forceinline__ void ldm_x4_t(uint32_t* r, uint32_t addr) {
    asm volatile(
        "ldmatrix.sync.aligned.m8n8.x4.trans.shared.b16 {%0,%1,%2,%3}, [%4];"
        : "=r"(r[0]), "=r"(r[1]), "=r"(r[2]), "=r"(r[3]) : "r"(addr));
}
__device__ __forceinline__ uint32_t pack2bf(float a, float b) {
    __nv_bfloat162 h = __floats2bfloat162_rn(a, b);
    return *reinterpret_cast<uint32_t*>(&h);
}
__device__ __forceinline__ void split2(float x, float y, uint32_t& hi,
                                       uint32_t& lo) {
    __nv_bfloat16 hx = __float2bfloat16(x);
    __nv_bfloat16 hy = __float2bfloat16(y);
    __nv_bfloat162 hp;
    hp.x = hx; hp.y = hy;
    hi = *reinterpret_cast<uint32_t*>(&hp);
    lo = pack2bf(x - __bfloat162float(hx), y - __bfloat162float(hy));
}
// exp on the FMA pipe. Exact 1.0 at x==0; safe for -FLT_MAX inputs.
__device__ __forceinline__ float fexp(float x) {
    float y = x * 1.4426950408889634f;
    y = fmaxf(y, -126.0f);
    float n = rintf(y);
    float f = y - n;
    float t = f * 0.6931471805599453f;
    float p = 1.9841270e-4f;
    p = fmaf(p, t, 1.3888889e-3f);
    p = fmaf(p, t, 8.3333333e-3f);
    p = fmaf(p, t, 4.1666668e-2f);
    p = fmaf(p, t, 0.16666667f);
    p = fmaf(p, t, 0.5f);
    p = fmaf(p, t, 1.0f);
    p = fmaf(p, t, 1.0f);
    return __int_as_float(__float_as_int(p) + ((int)n << 23));
}
__device__ __forceinline__ void cp16(uint32_t s, const void* g) {
    asm volatile("cp.async.cg.shared.global [%0], [%1], 16;" :: "r"(s), "l"(g));
}
#define CP_COMMIT() asm volatile("cp.async.commit_group;" ::: "memory")
#define CP_WAIT(n) asm volatile("cp.async.wait_group %0;" :: "n"(n) : "memory")

// ===========================================================================
// one-shot split kernels
// ===========================================================================
__global__ __launch_bounds__(256) void splitV(const float* __restrict__ in,
                                              __nv_bfloat16* __restrict__ hi,
                                              __nv_bfloat16* __restrict__ lo) {
    int i = blockIdx.x * 256 + threadIdx.x;
    float4 v = ((const float4*)in)[i];
    uint32_t h01, l01, h23, l23;
    split2(v.x, v.y, h01, l01);
    split2(v.z, v.w, h23, l23);
    ((uint2*)hi)[i] = make_uint2(h01, h23);
    ((uint2*)lo)[i] = make_uint2(l01, l23);
}
// W [k][n] fp32 -> WT [n][k] bf16 hi/lo
__global__ __launch_bounds__(256) void splitT(const float* __restrict__ W,
                                              __nv_bfloat16* __restrict__ WhT,
                                              __nv_bfloat16* __restrict__ WlT) {
    __shared__ float t[32][33];
    const int n0 = blockIdx.x * 32, k0 = blockIdx.y * 32;
    const int tx = threadIdx.x & 31, ty = threadIdx.x >> 5;  // 32x8
#pragma unroll
    for (int r = ty; r < 32; r += 8)
        t[r][tx] = W[(size_t)(k0 + r) * GN + n0 + tx];
    __syncthreads();
#pragma unroll
    for (int r = ty; r < 32; r += 8) {
        float v = t[tx][r];
        __nv_bfloat16 h = __float2bfloat16(v);
        WhT[(size_t)(n0 + r) * GK + k0 + tx] = h;
        WlT[(size_t)(n0 + r) * GK + k0 + tx] =
            __float2bfloat16(v - __bfloat162float(h));
    }
}

// ===========================================================================
// bf16 split GEMM, cp.async double-buffered (unchanged from R7 - WIN).
// ===========================================================================
#define BKT 32
#define KT (GK / BKT)  // 32
#define KPAD 40
#define TILE_E (128 * KPAD)
#define TILE_BY (TILE_E * 2)
#define GEMM_SMEM (8 * TILE_BY)

template <int MODE>
__global__ __launch_bounds__(256) void gemm_bf(
    const __nv_bfloat16* __restrict__ Ahg, const __nv_bfloat16* __restrict__ Alg,
    const __nv_bfloat16* __restrict__ BhT, const __nv_bfloat16* __restrict__ BlT,
    float* __restrict__ C, __nv_bfloat16* __restrict__ Chi,
    __nv_bfloat16* __restrict__ Clo) {
    extern __shared__ __nv_bfloat16 dsm[];
    const uint32_t sbase = (uint32_t)__cvta_generic_to_shared(dsm);

    const int tid = threadIdx.x;
    const int wid = tid >> 5;
    const int lane = tid & 31;
    const int g = lane >> 2;
    const int tg = lane & 3;
    const int wm = (wid & 3) * 32;
    const int wn = (wid >> 2) * 64;
    const int m0 = blockIdx.y * 128;
    const int n0 = blockIdx.x * 128;

    const int r0 = tid >> 2;
    const int ck = (tid & 3) * 8;
    const uint32_t so0 = (uint32_t)(r0 * KPAD + ck) * 2;
    const uint32_t so1 = (uint32_t)((r0 + 64) * KPAD + ck) * 2;

    float acc[2][8][4];
#pragma unroll
    for (int i = 0; i < 2; i++)
#pragma unroll
        for (int j = 0; j < 8; j++)
#pragma unroll
            for (int r = 0; r < 4; r++) acc[i][j][r] = 0.f;

    auto issue = [&](int t, int st) {
        const int k0 = t * BKT;
        const uint32_t b = sbase + (uint32_t)st * 4 * TILE_BY;
        size_t gA0 = (size_t)(m0 + r0) * GK + k0 + ck;
        size_t gA1 = gA0 + (size_t)64 * GK;
        size_t gB0 = (size_t)(n0 + r0) * GK + k0 + ck;
        size_t gB1 = gB0 + (size_t)64 * GK;
        cp16(b + so0, Ahg + gA0);
        cp16(b + so1, Ahg + gA1);
        cp16(b + TILE_BY + so0, Alg + gA0);
        cp16(b + TILE_BY + so1, Alg + gA1);
        cp16(b + 2 * TILE_BY + so0, BhT + gB0);
        cp16(b + 2 * TILE_BY + so1, BhT + gB1);
        cp16(b + 3 * TILE_BY + so0, BlT + gB0);
        cp16(b + 3 * TILE_BY + so1, BlT + gB1);
    };

    issue(0, 0);
    CP_COMMIT();

    for (int t = 0; t < KT; t++) {
        const int st = t & 1;
        if (t + 1 < KT) {
            issue(t + 1, st ^ 1);
            CP_COMMIT();
            CP_WAIT(1);
        } else {
            CP_WAIT(0);
        }
        __syncthreads();

        const __nv_bfloat16* sAh = dsm + (size_t)st * 4 * TILE_E;
        const __nv_bfloat16* sAl = sAh + TILE_E;
        const __nv_bfloat16* sBh = sAl + TILE_E;
        const __nv_bfloat16* sBl = sBh + TILE_E;

#pragma unroll
        for (int kh = 0; kh < 2; kh++) {
            const int kb = kh * 16;
            const int c = kb + 2 * tg;
            uint32_t afh[2][4], afl[2][4];
#pragma unroll
            for (int mt = 0; mt < 2; mt++) {
                int r = wm + mt * 16 + g;
                afh[mt][0] = *(const uint32_t*)&sAh[r * KPAD + c];
                afh[mt][1] = *(const uint32_t*)&sAh[(r + 8) * KPAD + c];
                afh[mt][2] = *(const uint32_t*)&sAh[r * KPAD + c + 8];
                afh[mt][3] = *(const uint32_t*)&sAh[(r + 8) * KPAD + c + 8];
                afl[mt][0] = *(const uint32_t*)&sAl[r * KPAD + c];
                afl[mt][1] = *(const uint32_t*)&sAl[(r + 8) * KPAD + c];
                afl[mt][2] = *(const uint32_t*)&sAl[r * KPAD + c + 8];
                afl[mt][3] = *(const uint32_t*)&sAl[(r + 8) * KPAD + c + 8];
            }
            uint32_t bfh[8][2], bfl[8][2];
#pragma unroll
            for (int nt = 0; nt < 8; nt++) {
                int n = wn + nt * 8 + g;
                bfh[nt][0] = *(const uint32_t*)&sBh[n * KPAD + c];
                bfh[nt][1] = *(const uint32_t*)&sBh[n * KPAD + c + 8];
                bfl[nt][0] = *(const uint32_t*)&sBl[n * KPAD + c];
                bfl[nt][1] = *(const uint32_t*)&sBl[n * KPAD + c + 8];
            }
#pragma unroll
            for (int mt = 0; mt < 2; mt++)
#pragma unroll
                for (int nt = 0; nt < 8; nt++) {
                    mma_bf16(acc[mt][nt], afh[mt], bfh[nt]);
                    mma_bf16(acc[mt][nt], afh[mt], bfl[nt]);
                    mma_bf16(acc[mt][nt], afl[mt], bfh[nt]);
                }
        }
        __syncthreads();
    }

#pragma unroll
    for (int mt = 0; mt < 2; mt++) {
        int rbase = m0 + wm + mt * 16 + g;
#pragma unroll
        for (int nt = 0; nt < 8; nt++) {
            int cbase = n0 + wn + nt * 8 + 2 * tg;
            if (MODE == 0) {
                float* p0 = C + (size_t)rbase * GN + cbase;
                float* p1 = C + (size_t)(rbase + 8) * GN + cbase;
                p0[0] = acc[mt][nt][0];
                p0[1] = acc[mt][nt][1];
                p1[0] = acc[mt][nt][2];
                p1[1] = acc[mt][nt][3];
            } else {
                uint32_t h01, l01, h23, l23;
                split2(acc[mt][nt][0], acc[mt][nt][1], h01, l01);
                split2(acc[mt][nt][2], acc[mt][nt][3], h23, l23);
                *(uint32_t*)(Chi + (size_t)rbase * GN + cbase) = h01;
                *(uint32_t*)(Clo + (size_t)rbase * GN + cbase) = l01;
                *(uint32_t*)(Chi + (size_t)(rbase + 8) * GN + cbase) = h23;
                *(uint32_t*)(Clo + (size_t)(rbase + 8) * GN + cbase) = l23;
            }
        }
    }
}

// ===========================================================================
// HMMA flash attention v2: BM=128, 8 warps, cp.async double-buffered K/V,
// ldmatrix fragment loads (V via .trans from natural [key][dh] layout).
// Numerics identical to validated R5-R7 path.
// ===========================================================================
#define APAD 72
// element offsets in smem (bf16 units)
#define OQH 0
#define OQL (128 * APAD)               // 9216
#define OST (2 * 128 * APAD)           // 18432: stage base
#define STG (4 * 64 * APAD)            // 18432: stage stride (Kh,Kl,Vh,Vl)
#define OKL (64 * APAD)                // 4608
#define OVH (2 * 64 * APAD)
#define OVL (3 * 64 * APAD)
#define MASK_BYTE ((OST + 2 * STG) * 2)  // 110592
#define SMEM_ATTN (MASK_BYTE + 2 * 64 * 4)

__global__ void __launch_bounds__(256, 2) attn_mma(
    const __nv_bfloat16* __restrict__ Qh_, const __nv_bfloat16* __restrict__ Ql_,
    const __nv_bfloat16* __restrict__ Kh_, const __nv_bfloat16* __restrict__ Kl_,
    const __nv_bfloat16* __restrict__ Vh_, const __nv_bfloat16* __restrict__ Vl_,
    const int* __restrict__ maskg, __nv_bfloat16* __restrict__ Ch,
    __nv_bfloat16* __restrict__ Cl) {
    extern __shared__ __nv_bfloat16 sma[];
    const uint32_t sb = (uint32_t)__cvta_generic_to_shared(sma);
    int* mks = (int*)((char*)sma + MASK_BYTE);

    const int tid = threadIdx.x;
    const int wid = tid >> 5;
    const int lane = tid & 31;
    const int g = lane >> 2;
    const int tg = lane & 3;
    const int wm = wid * 16;
    const int q0 = blockIdx.x * 128;
    const int bh = blockIdx.y;
    const int b = bh >> 4;
    const int h = bh & 15;
    const size_t tokBase = (size_t)b * L_SEQ;
    const int colH = h * DH;
    const int* mb = maskg + b * L_SEQ;

    // ---- Q tiles hi/lo via cp.async (128 rows x 64 cols)
#pragma unroll
    for (int j = 0; j < 4; j++) {
        int f = tid + j * 256;
        int r = f >> 3;
        int c8 = (f & 7) * 8;
        size_t gq = (tokBase + q0 + r) * D_MODEL + colH + c8;
        cp16(sb + (uint32_t)(OQH + r * APAD + c8) * 2, Qh_ + gq);
        cp16(sb + (uint32_t)(OQL + r * APAD + c8) * 2, Ql_ + gq);
    }
    // ---- K/V + mask tile issue
    auto issueKV = [&](int kt, int s) {
        const uint32_t base = OST + s * STG;
#pragma unroll
        for (int j = 0; j < 2; j++) {
            int f = tid + j * 256;
            int r = f >> 3;
            int c8 = (f & 7) * 8;
            size_t gk = (tokBase + kt * 64 + r) * D_MODEL + colH + c8;
            uint32_t so = (uint32_t)(r * APAD + c8) * 2;
            cp16(sb + (base)*2 + so, Kh_ + gk);
            cp16(sb + (base + OKL) * 2 + so, Kl_ + gk);
            cp16(sb + (base + OVH) * 2 + so, Vh_ + gk);
            cp16(sb + (base + OVL) * 2 + so, Vl_ + gk);
        }
        if (tid < 16)
            cp16(sb + MASK_BYTE + s * 256 + tid * 16, mb + kt * 64 + tid * 4);
    };
    issueKV(0, 0);
    CP_COMMIT();

    const int mq0 = mb[q0 + wm + g];
    const int mq1 = mb[q0 + wm + g + 8];

    float m0 = -FLT_MAX, m1 = -FLT_MAX, l0 = 0.f, l1 = 0.f;
    float oacc[8][4];
#pragma unroll
    for (int i = 0; i < 8; i++)
#pragma unroll
        for (int j = 0; j < 4; j++) oacc[i][j] = 0.f;

    const float SCALE = 0.03125f;
    const float MASKV = -FLT_MAX * 0.03125f;

    // ldmatrix address components (loop-invariant)
    const uint32_t qBase =
        sb + (uint32_t)(OQH + (wm + (lane & 15)) * APAD + ((lane >> 4) & 1) * 8) * 2;
    const int kRow = (lane & 7) + ((lane >> 4) & 1) * 8;  // n-row within 16
    const int kCol = ((lane >> 3) & 1) * 8;               // k-col 0/8
    const int vRow = (lane & 7) + ((lane >> 3) & 1) * 8;  // key within 16
    const int vCol = ((lane >> 4) & 1) * 8;               // dh 0/8 within pair

    for (int kt = 0; kt < L_SEQ / 64; kt++) {
        const int st = kt & 1;
        if (kt + 1 < L_SEQ / 64) {
            issueKV(kt + 1, st ^ 1);
            CP_COMMIT();
            CP_WAIT(1);
        } else {
            CP_WAIT(0);
        }
        __syncthreads();

        const uint32_t stE = OST + st * STG;
        const int* mkt = mks + st * 64;

        // ---- S = Q K^T
        float sacc[8][4];
#pragma unroll
        for (int i = 0; i < 8; i++)
#pragma unroll
            for (int j = 0; j < 4; j++) sacc[i][j] = 0.f;

#pragma unroll
        for (int kk = 0; kk < 4; kk++) {
            uint32_t aqh[4], aql[4];
            ldm_x4(aqh, qBase + kk * 32);
            ldm_x4(aql, qBase + OQL * 2 + kk * 32);
#pragma unroll
            for (int ntp = 0; ntp < 4; ntp++) {
                const int nb = ntp * 16;
                uint32_t ka =
                    sb + (uint32_t)(stE + (nb + kRow) * APAD + kk * 16 + kCol) * 2;
                uint32_t bh4[4], bl4[4];
                ldm_x4(bh4, ka);
                ldm_x4(bl4, ka + OKL * 2);
                mma_bf16(sacc[2 * ntp], aqh, bh4);
                mma_bf16(sacc[2 * ntp], aqh, bl4);
                mma_bf16(sacc[2 * ntp], aql, bh4);
                mma_bf16(sacc[2 * ntp + 1], aqh, bh4 + 2);
                mma_bf16(sacc[2 * ntp + 1], aqh, bl4 + 2);
                mma_bf16(sacc[2 * ntp + 1], aql, bh4 + 2);
            }
        }

        // ---- mask + scale (validated semantics)
#pragma unroll
        for (int nt = 0; nt < 8; nt++) {
            int mkA = mkt[nt * 8 + 2 * tg];
            int mkB = mkt[nt * 8 + 2 * tg + 1];
            sacc[nt][0] = (mq0 && mkA) ? sacc[nt][0] * SCALE : MASKV;
            sacc[nt][1] = (mq0 && mkB) ? sacc[nt][1] * SCALE : MASKV;
            sacc[nt][2] = (mq1 && mkA) ? sacc[nt][2] * SCALE : MASKV;
            sacc[nt][3] = (mq1 && mkB) ? sacc[nt][3] * SCALE : MASKV;
        }

        // ---- online softmax
        float rx0 = -FLT_MAX, rx1 = -FLT_MAX;
#pragma unroll
        for (int nt = 0; nt < 8; nt++) {
            rx0 = fmaxf(rx0, fmaxf(sacc[nt][0], sacc[nt][1]));
            rx1 = fmaxf(rx1, fmaxf(sacc[nt][2], sacc[nt][3]));
        }
        rx0 = fmaxf(rx0, __shfl_xor_sync(0xffffffffu, rx0, 1));
        rx0 = fmaxf(rx0, __shfl_xor_sync(0xffffffffu, rx0, 2));
        rx1 = fmaxf(rx1, __shfl_xor_sync(0xffffffffu, rx1, 1));
        rx1 = fmaxf(rx1, __shfl_xor_sync(0xffffffffu, rx1, 2));

        float mn0 = fmaxf(m0, rx0);
        float mn1 = fmaxf(m1, rx1);
        float corr0 = fexp(m0 - mn0);
        float corr1 = fexp(m1 - mn1);
        float s0 = 0.f, s1 = 0.f;
#pragma unroll
        for (int nt = 0; nt < 8; nt++) {
            sacc[nt][0] = fexp(sacc[nt][0] - mn0);
            sacc[nt][1] = fexp(sacc[nt][1] - mn0);
            sacc[nt][2] = fexp(sacc[nt][2] - mn1);
            sacc[nt][3] = fexp(sacc[nt][3] - mn1);
            s0 += sacc[nt][0] + sacc[nt][1];
            s1 += sacc[nt][2] + sacc[nt][3];
        }
        s0 += __shfl_xor_sync(0xffffffffu, s0, 1);
        s0 += __shfl_xor_sync(0xffffffffu, s0, 2);
        s1 += __shfl_xor_sync(0xffffffffu, s1, 1);
        s1 += __shfl_xor_sync(0xffffffffu, s1, 2);
        l0 = l0 * corr0 + s0;
        l1 = l1 * corr1 + s1;
        m0 = mn0;
        m1 = mn1;
#pragma unroll
        for (int nto = 0; nto < 8; nto++) {
            oacc[nto][0] *= corr0;
            oacc[nto][1] *= corr0;
            oacc[nto][2] *= corr1;
            oacc[nto][3] *= corr1;
        }

        // ---- O += P V (P frags register-resident; V via ldmatrix.trans)
#pragma unroll
        for (int kk = 0; kk < 4; kk++) {
            uint32_t aph[4], apl[4];
            split2(sacc[2 * kk][0], sacc[2 * kk][1], aph[0], apl[0]);
            split2(sacc[2 * kk][2], sacc[2 * kk][3], aph[1], apl[1]);
            split2(sacc[2 * kk + 1][0], sacc[2 * kk + 1][1], aph[2], apl[2]);
            split2(sacc[2 * kk + 1][2], sacc[2 * kk + 1][3], aph[3], apl[3]);
#pragma unroll
            for (int dbp = 0; dbp < 4; dbp++) {
                uint32_t va =
                    sb + (uint32_t)(stE + OVH + (kk * 16 + vRow) * APAD +
                                    dbp * 16 + vCol) * 2;
                uint32_t vh4[4], vl4[4];
                ldm_x4_t(vh4, va);
                ldm_x4_t(vl4, va + OKL * 2);  // OVL - OVH = OKL
                mma_bf16(oacc[2 * dbp], aph, vh4);
                mma_bf16(oacc[2 * dbp], aph, vl4);
                mma_bf16(oacc[2 * dbp], apl, vh4);
                mma_bf16(oacc[2 * dbp + 1], aph, vh4 + 2);
                mma_bf16(oacc[2 * dbp + 1], aph, vl4 + 2);
                mma_bf16(oacc[2 * dbp + 1], apl, vh4 + 2);
            }
        }
        __syncthreads();
    }

    // ---- epilogue: normalize + split to bf16 hi/lo ctx
    const float inv0 = 1.0f / l0;
    const float inv1 = 1.0f / l1;
    const size_t r0o = (tokBase + q0 + wm + g) * D_MODEL;
    const size_t r1o = r0o + 8 * D_MODEL;
#pragma unroll
    for (int nto = 0; nto < 8; nto++) {
        int cb = colH + nto * 8 + 2 * tg;
        uint32_t h01, l01, h23, l23;
        split2(oacc[nto][0] * inv0, oacc[nto][1] * inv0, h01, l01);
        split2(oacc[nto][2] * inv1, oacc[nto][3] * inv1, h23, l23);
        *(uint32_t*)(Ch + r0o + cb) = h01;
        *(uint32_t*)(Cl + r0o + cb) = l01;
        *(uint32_t*)(Ch + r1o + cb) = h23;
        *(uint32_t*)(Cl + r1o + cb) = l23;
    }
}

// ---------------------------------------------------------------------------
extern "C" void kernel_launch(void* const* d_in, const int* in_sizes, int n_in,
                              void* d_out, int out_size) {
    const float* x = (const float*)d_in[0];
    const int* mask = (const int*)d_in[1];
    const float* w[4] = {(const float*)d_in[2], (const float*)d_in[3],
                         (const float*)d_in[4], (const float*)d_in[5]};
    float* out = (float*)d_out;

    __nv_bfloat16 *xh, *xl, *qh, *ql, *kh, *kl, *vh, *vl, *ch, *cl, *wTh, *wTl;
    cudaGetSymbolAddress((void**)&xh, g_xh);
    cudaGetSymbolAddress((void**)&xl, g_xl);
    cudaGetSymbolAddress((void**)&qh, g_qh);
    cudaGetSymbolAddress((void**)&ql, g_ql);
    cudaGetSymbolAddress((void**)&kh, g_kh);
    cudaGetSymbolAddress((void**)&kl, g_kl);
    cudaGetSymbolAddress((void**)&vh, g_vh);
    cudaGetSymbolAddress((void**)&vl, g_vl);
    cudaGetSymbolAddress((void**)&ch, g_ch);
    cudaGetSymbolAddress((void**)&cl, g_cl);
    cudaGetSymbolAddress((void**)&wTh, g_wTh);
    cudaGetSymbolAddress((void**)&wTl, g_wTl);

    cudaFuncSetAttribute(attn_mma, cudaFuncAttributeMaxDynamicSharedMemorySize,
                         SMEM_ATTN);
    cudaFuncSetAttribute(gemm_bf<0>,
                         cudaFuncAttributeMaxDynamicSharedMemorySize, GEMM_SMEM);
    cudaFuncSetAttribute(gemm_bf<1>,
                         cudaFuncAttributeMaxDynamicSharedMemorySize, GEMM_SMEM);

    // 1) split inputs
    splitV<<<(M_TOK * D_MODEL / 4) / 256, 256>>>(x, xh, xl);
    for (int i = 0; i < 4; i++)
        splitT<<<dim3(GN / 32, GK / 32), 256>>>(w[i], wTh + (size_t)i * GK * GN,
                                                wTl + (size_t)i * GK * GN);

    // 2) QKV projections
    dim3 gg(GN / 128, M_TOK / 128);
    gemm_bf<1><<<gg, 256, GEMM_SMEM>>>(xh, xl, wTh + 0 * (size_t)GK * GN,
                                       wTl + 0 * (size_t)GK * GN, nullptr, qh, ql);
    gemm_bf<1><<<gg, 256, GEMM_SMEM>>>(xh, xl, wTh + 1 * (size_t)GK * GN,
                                       wTl + 1 * (size_t)GK * GN, nullptr, kh, kl);
    gemm_bf<1><<<gg, 256, GEMM_SMEM>>>(xh, xl, wTh + 2 * (size_t)GK * GN,
                                       wTl + 2 * (size_t)GK * GN, nullptr, vh, vl);

    // 3) attention
    attn_mma<<<dim3(L_SEQ / 128, NB * NH), 256, SMEM_ATTN>>>(qh, ql, kh, kl, vh,
                                                             vl, mask, ch, cl);

    // 4) output projection
    gemm_bf<0><<<gg, 256, GEMM_SMEM>>>(ch, cl, wTh + 3 * (size_t)GK * GN,
                                       wTl + 3 * (size_t)GK * GN, out, nullptr,
                                       nullptr);
}